// round 1
// baseline (speedup 1.0000x reference)
#include <cuda_runtime.h>
#include <cuda_bf16.h>
#include <math.h>

// Problem constants
#define B   2
#define S   2048
#define D   1024
#define H   16
#define DH  64
#define ROWS (B*S)           // 4096
#define EPS 1e-5f

// ---------------- scratch (device globals; no allocation allowed) ----------
__device__ float g_xn [ROWS * D];
__device__ float g_q  [ROWS * D];
__device__ float g_k  [ROWS * D];
__device__ float g_v  [ROWS * D];
__device__ float g_att[ROWS * D];

// ---------------- LayerNorm: one block per row --------------------------
__global__ void ln_kernel(const float* __restrict__ x,
                          const float* __restrict__ gamma,
                          const float* __restrict__ beta,
                          float* __restrict__ out) {
    int row = blockIdx.x;
    const float* xr = x + (size_t)row * D;
    float* orow = out + (size_t)row * D;

    float vals[4];
    float sum = 0.f, sq = 0.f;
#pragma unroll
    for (int i = 0; i < 4; i++) {
        float v = xr[threadIdx.x + i * 256];
        vals[i] = v;
        sum += v; sq += v * v;
    }
#pragma unroll
    for (int o = 16; o >= 1; o >>= 1) {
        sum += __shfl_xor_sync(0xffffffffu, sum, o);
        sq  += __shfl_xor_sync(0xffffffffu, sq , o);
    }
    __shared__ float ssum[8], ssq[8];
    int warp = threadIdx.x >> 5, lane = threadIdx.x & 31;
    if (lane == 0) { ssum[warp] = sum; ssq[warp] = sq; }
    __syncthreads();
    float ts = 0.f, tq = 0.f;
#pragma unroll
    for (int w = 0; w < 8; w++) { ts += ssum[w]; tq += ssq[w]; }
    float mu  = ts * (1.0f / D);
    float var = tq * (1.0f / D) - mu * mu;
    float rstd = rsqrtf(var + EPS);
#pragma unroll
    for (int i = 0; i < 4; i++) {
        int c = threadIdx.x + i * 256;
        orow[c] = (vals[i] - mu) * rstd * gamma[c] + beta[c];
    }
}

// ---------------- SGEMM with bias: C[M,N] = A[M,K] @ W[K,N] + bias -------
// 64x64 tile, 16-deep k slab, 256 threads, 4x4 micro-tile per thread.
__global__ void sgemm_bias(const float* __restrict__ A,
                           const float* __restrict__ W,
                           const float* __restrict__ bias,
                           float* __restrict__ C,
                           int M, int N, int K) {
    __shared__ float As[16][64];   // [k][m]  (A stored transposed)
    __shared__ float Bs[16][64];   // [k][n]

    int tid = threadIdx.x;
    int tx  = tid & 15;            // n-dir
    int ty  = tid >> 4;            // m-dir
    int mBase = blockIdx.y * 64;
    int nBase = blockIdx.x * 64;

    float acc[4][4] = {};

    int ra  = tid >> 2;            // 0..63 : A tile row
    int ca4 = (tid & 3) << 2;      // 0..12 : A tile col (float4)
    int rb  = tid >> 4;            // 0..15 : W tile row
    int cb4 = (tid & 15) << 2;     // 0..60 : W tile col (float4)

    for (int k0 = 0; k0 < K; k0 += 16) {
        float4 a = *(const float4*)(A + (size_t)(mBase + ra) * K + k0 + ca4);
        As[ca4 + 0][ra] = a.x;
        As[ca4 + 1][ra] = a.y;
        As[ca4 + 2][ra] = a.z;
        As[ca4 + 3][ra] = a.w;
        float4 b = *(const float4*)(W + (size_t)(k0 + rb) * N + nBase + cb4);
        *(float4*)(&Bs[rb][cb4]) = b;
        __syncthreads();

#pragma unroll
        for (int k = 0; k < 16; k++) {
            float4 a4 = *(float4*)(&As[k][ty * 4]);
            float4 b4 = *(float4*)(&Bs[k][tx * 4]);
            float aa[4] = {a4.x, a4.y, a4.z, a4.w};
            float bb[4] = {b4.x, b4.y, b4.z, b4.w};
#pragma unroll
            for (int i = 0; i < 4; i++)
#pragma unroll
                for (int j = 0; j < 4; j++)
                    acc[i][j] = fmaf(aa[i], bb[j], acc[i][j]);
        }
        __syncthreads();
    }

    float4 bi = *(const float4*)(bias + nBase + tx * 4);
    float bb[4] = {bi.x, bi.y, bi.z, bi.w};
#pragma unroll
    for (int i = 0; i < 4; i++) {
        int row = mBase + ty * 4 + i;
        float4 o;
        o.x = acc[i][0] + bb[0];
        o.y = acc[i][1] + bb[1];
        o.z = acc[i][2] + bb[2];
        o.w = acc[i][3] + bb[3];
        *(float4*)(C + (size_t)row * N + nBase + tx * 4) = o;
    }
}

// ---------------- Flash-style attention -----------------------------------
// grid: (S/64, B*H). Each block: 64 queries of one (b,h). Online softmax over
// 32 key tiles of 64. 256 threads, 4x4 micro-tiles.
__global__ void attn_kernel(const float* __restrict__ Q,
                            const float* __restrict__ K,
                            const float* __restrict__ V,
                            float* __restrict__ O) {
    extern __shared__ float sm[];
    float* Qst = sm;            // [64][64], d-major: Qst[d*64 + r], pre-scaled
    float* Kst = sm + 4096;     // [64][64], d-major
    float* Vs  = sm + 8192;     // [64][64], key-major: Vs[k*64 + d]
    float* Ps  = sm + 12288;    // [64][65]

    int tid = threadIdx.x;
    int tx = tid & 15, ty = tid >> 4;
    int bh = blockIdx.y;
    int b = bh >> 4, h = bh & 15;
    int qbase = blockIdx.x * 64;

    const float* Qg = Q + ((size_t)(b * S + qbase) * D + h * DH);
    const float* Kg = K + ((size_t)(b * S) * D + h * DH);
    const float* Vg = V + ((size_t)(b * S) * D + h * DH);

    // load Q tile (transposed to d-major, scaled by 1/sqrt(DH))
#pragma unroll
    for (int it = 0; it < 4; it++) {
        int lin = tid + it * 256;
        int r  = lin >> 4;
        int c4 = (lin & 15) << 2;
        float4 q4 = *(const float4*)(Qg + (size_t)r * D + c4);
        Qst[(c4 + 0) * 64 + r] = q4.x * 0.125f;
        Qst[(c4 + 1) * 64 + r] = q4.y * 0.125f;
        Qst[(c4 + 2) * 64 + r] = q4.z * 0.125f;
        Qst[(c4 + 3) * 64 + r] = q4.w * 0.125f;
    }

    float m_prev[4], l[4], acc[4][4];
#pragma unroll
    for (int i = 0; i < 4; i++) {
        m_prev[i] = -INFINITY; l[i] = 0.f;
#pragma unroll
        for (int j = 0; j < 4; j++) acc[i][j] = 0.f;
    }

    for (int kt = 0; kt < S / 64; kt++) {
        __syncthreads();   // previous phase-B reads of Kst/Vs done
        const float* Kgt = Kg + (size_t)kt * 64 * D;
        const float* Vgt = Vg + (size_t)kt * 64 * D;
#pragma unroll
        for (int it = 0; it < 4; it++) {
            int lin = tid + it * 256;
            int r  = lin >> 4;
            int c4 = (lin & 15) << 2;
            float4 k4 = *(const float4*)(Kgt + (size_t)r * D + c4);
            Kst[(c4 + 0) * 64 + r] = k4.x;
            Kst[(c4 + 1) * 64 + r] = k4.y;
            Kst[(c4 + 2) * 64 + r] = k4.z;
            Kst[(c4 + 3) * 64 + r] = k4.w;
            float4 v4 = *(const float4*)(Vgt + (size_t)r * D + c4);
            *(float4*)(Vs + r * 64 + c4) = v4;
        }
        __syncthreads();

        // phase A: S = Q K^T (scaled)
        float s[4][4] = {};
#pragma unroll 16
        for (int d = 0; d < 64; d++) {
            float4 q4 = *(float4*)(Qst + d * 64 + ty * 4);
            float4 k4 = *(float4*)(Kst + d * 64 + tx * 4);
            float qa[4] = {q4.x, q4.y, q4.z, q4.w};
            float ka[4] = {k4.x, k4.y, k4.z, k4.w};
#pragma unroll
            for (int i = 0; i < 4; i++)
#pragma unroll
                for (int j = 0; j < 4; j++)
                    s[i][j] = fmaf(qa[i], ka[j], s[i][j]);
        }

        // online softmax update per query row
#pragma unroll
        for (int i = 0; i < 4; i++) {
            float mx = fmaxf(fmaxf(s[i][0], s[i][1]), fmaxf(s[i][2], s[i][3]));
#pragma unroll
            for (int o = 8; o >= 1; o >>= 1)
                mx = fmaxf(mx, __shfl_xor_sync(0xffffffffu, mx, o));
            float mn = fmaxf(m_prev[i], mx);
            float alpha = __expf(m_prev[i] - mn);
            float rs = 0.f;
#pragma unroll
            for (int j = 0; j < 4; j++) {
                float p = __expf(s[i][j] - mn);
                s[i][j] = p;
                rs += p;
            }
#pragma unroll
            for (int o = 8; o >= 1; o >>= 1)
                rs += __shfl_xor_sync(0xffffffffu, rs, o);
            l[i] = l[i] * alpha + rs;
            m_prev[i] = mn;
#pragma unroll
            for (int j = 0; j < 4; j++) acc[i][j] *= alpha;
#pragma unroll
            for (int j = 0; j < 4; j++)
                Ps[(ty * 4 + i) * 65 + tx * 4 + j] = s[i][j];
        }
        __syncthreads();

        // phase B: acc += P @ V
#pragma unroll 16
        for (int kk = 0; kk < 64; kk++) {
            float4 v4 = *(float4*)(Vs + kk * 64 + tx * 4);
            float va[4] = {v4.x, v4.y, v4.z, v4.w};
            float pa[4];
#pragma unroll
            for (int i = 0; i < 4; i++)
                pa[i] = Ps[(ty * 4 + i) * 65 + kk];
#pragma unroll
            for (int i = 0; i < 4; i++)
#pragma unroll
                for (int j = 0; j < 4; j++)
                    acc[i][j] = fmaf(pa[i], va[j], acc[i][j]);
        }
    }

    // epilogue: normalize & store
#pragma unroll
    for (int i = 0; i < 4; i++) {
        float rl = 1.0f / l[i];
        int row = qbase + ty * 4 + i;
        float4 o;
        o.x = acc[i][0] * rl;
        o.y = acc[i][1] * rl;
        o.z = acc[i][2] * rl;
        o.w = acc[i][3] * rl;
        *(float4*)(O + ((size_t)(b * S + row) * D + h * DH + tx * 4)) = o;
    }
}

// ---------------- launch ---------------------------------------------------
extern "C" void kernel_launch(void* const* d_in, const int* in_sizes, int n_in,
                              void* d_out, int out_size) {
    const float* x     = (const float*)d_in[0];
    const float* gamma = (const float*)d_in[1];
    const float* beta  = (const float*)d_in[2];
    const float* wq    = (const float*)d_in[3];
    const float* bq    = (const float*)d_in[4];
    const float* wk    = (const float*)d_in[5];
    const float* bk    = (const float*)d_in[6];
    const float* wv    = (const float*)d_in[7];
    const float* bv    = (const float*)d_in[8];
    const float* wo    = (const float*)d_in[9];
    const float* bo    = (const float*)d_in[10];
    float* out = (float*)d_out;

    float *xn, *q, *k, *v, *att;
    cudaGetSymbolAddress((void**)&xn,  g_xn);
    cudaGetSymbolAddress((void**)&q,   g_q);
    cudaGetSymbolAddress((void**)&k,   g_k);
    cudaGetSymbolAddress((void**)&v,   g_v);
    cudaGetSymbolAddress((void**)&att, g_att);

    // 1. LayerNorm
    ln_kernel<<<ROWS, 256>>>(x, gamma, beta, xn);

    // 2-4. Q/K/V projections
    dim3 ggrid(D / 64, ROWS / 64);   // (16, 64)
    sgemm_bias<<<ggrid, 256>>>(xn, wq, bq, q, ROWS, D, D);
    sgemm_bias<<<ggrid, 256>>>(xn, wk, bk, k, ROWS, D, D);
    sgemm_bias<<<ggrid, 256>>>(xn, wv, bv, v, ROWS, D, D);

    // 5. attention
    int smem = (3 * 4096 + 64 * 65) * (int)sizeof(float);  // 65792 B
    cudaFuncSetAttribute(attn_kernel,
                         cudaFuncAttributeMaxDynamicSharedMemorySize, smem);
    dim3 agrid(S / 64, B * H);       // (32, 32)
    attn_kernel<<<agrid, 256, smem>>>(q, k, v, att);

    // 6. output projection
    sgemm_bias<<<ggrid, 256>>>(att, wo, bo, out, ROWS, D, D);
}

// round 2
// speedup vs baseline: 2.8527x; 2.8527x over previous
#include <cuda_runtime.h>
#include <cuda_bf16.h>
#include <math.h>
#include <stdint.h>

// Problem constants
#define B   2
#define S   2048
#define D   1024
#define H   16
#define DH  64
#define ROWS (B*S)           // 4096
#define EPS 1e-5f

// ---------------- scratch (device globals; no allocation allowed) ----------
__device__ float g_xn [ROWS * D];
__device__ float g_q  [ROWS * D];
__device__ float g_k  [ROWS * D];
__device__ float g_v  [ROWS * D];
__device__ float g_att[ROWS * D];

// ---------------- helpers ---------------------------------------------------
__device__ __forceinline__ float cvt_tf32f(float x) {
    uint32_t u;
    asm("cvt.rna.tf32.f32 %0, %1;" : "=r"(u) : "f"(x));
    return __uint_as_float(u);
}

#define MMA_TF32(c, a, b)                                                     \
    asm volatile(                                                             \
        "mma.sync.aligned.m16n8k8.row.col.f32.tf32.tf32.f32 "                 \
        "{%0,%1,%2,%3},{%4,%5,%6,%7},{%8,%9},{%0,%1,%2,%3};"                  \
        : "+f"((c)[0]), "+f"((c)[1]), "+f"((c)[2]), "+f"((c)[3])              \
        : "r"((a)[0]), "r"((a)[1]), "r"((a)[2]), "r"((a)[3]),                 \
          "r"((b)[0]), "r"((b)[1]))

// ---------------- LayerNorm: one block per row ------------------------------
__global__ void ln_kernel(const float* __restrict__ x,
                          const float* __restrict__ gamma,
                          const float* __restrict__ beta,
                          float* __restrict__ out) {
    int row = blockIdx.x;
    const float* xr = x + (size_t)row * D;
    float* orow = out + (size_t)row * D;

    float vals[4];
    float sum = 0.f, sq = 0.f;
#pragma unroll
    for (int i = 0; i < 4; i++) {
        float v = xr[threadIdx.x + i * 256];
        vals[i] = v;
        sum += v; sq += v * v;
    }
#pragma unroll
    for (int o = 16; o >= 1; o >>= 1) {
        sum += __shfl_xor_sync(0xffffffffu, sum, o);
        sq  += __shfl_xor_sync(0xffffffffu, sq , o);
    }
    __shared__ float ssum[8], ssq[8];
    int warp = threadIdx.x >> 5, lane = threadIdx.x & 31;
    if (lane == 0) { ssum[warp] = sum; ssq[warp] = sq; }
    __syncthreads();
    float ts = 0.f, tq = 0.f;
#pragma unroll
    for (int w = 0; w < 8; w++) { ts += ssum[w]; tq += ssq[w]; }
    float mu  = ts * (1.0f / D);
    float var = tq * (1.0f / D) - mu * mu;
    float rstd = rsqrtf(var + EPS);
#pragma unroll
    for (int i = 0; i < 4; i++) {
        int c = threadIdx.x + i * 256;
        orow[c] = (vals[i] - mu) * rstd * gamma[c] + beta[c];
    }
}

// ---------------- tf32 tensor-core GEMM: C = A@W + bias --------------------
// Block tile 128x128, BK=32, 256 threads = 8 warps (4 along M x 2 along N).
// Warp tile 32x64 = 2 m16 tiles x 8 n8 tiles.
__global__ void __launch_bounds__(256)
gemm_tf32(const float* __restrict__ A, const float* __restrict__ W,
          const float* __restrict__ bias, float* __restrict__ C,
          int K, int N) {
    __shared__ float As[128][36];   // [m][k], pad 4 -> frag banks 4g+k unique
    __shared__ float Bs[32][136];   // [k][n], pad 8 -> frag banks 8k+g unique

    int tid = threadIdx.x, lane = tid & 31, wid = tid >> 5;
    int wm = wid & 3, wn = wid >> 2;
    int mBase = blockIdx.y * 128, nBase = blockIdx.x * 128;

    float acc[2][8][4] = {};

    for (int k0 = 0; k0 < K; k0 += 32) {
        // load A tile 128x32 (tf32-converted)
#pragma unroll
        for (int i = 0; i < 4; i++) {
            int idx = tid + i * 256;
            int r = idx >> 3, c = (idx & 7) << 2;
            float4 v = *(const float4*)(A + (size_t)(mBase + r) * K + k0 + c);
            As[r][c + 0] = cvt_tf32f(v.x);
            As[r][c + 1] = cvt_tf32f(v.y);
            As[r][c + 2] = cvt_tf32f(v.z);
            As[r][c + 3] = cvt_tf32f(v.w);
        }
        // load B tile 32x128
#pragma unroll
        for (int i = 0; i < 4; i++) {
            int idx = tid + i * 256;
            int r = idx >> 5, c = (idx & 31) << 2;
            float4 v = *(const float4*)(W + (size_t)(k0 + r) * N + nBase + c);
            Bs[r][c + 0] = cvt_tf32f(v.x);
            Bs[r][c + 1] = cvt_tf32f(v.y);
            Bs[r][c + 2] = cvt_tf32f(v.z);
            Bs[r][c + 3] = cvt_tf32f(v.w);
        }
        __syncthreads();

#pragma unroll
        for (int ks = 0; ks < 4; ks++) {
            int kk = ks * 8;
            uint32_t a[2][4], b[8][2];
#pragma unroll
            for (int mt = 0; mt < 2; mt++) {
                int r = wm * 32 + mt * 16 + (lane >> 2);
                int kc = kk + (lane & 3);
                a[mt][0] = __float_as_uint(As[r][kc]);
                a[mt][1] = __float_as_uint(As[r + 8][kc]);
                a[mt][2] = __float_as_uint(As[r][kc + 4]);
                a[mt][3] = __float_as_uint(As[r + 8][kc + 4]);
            }
#pragma unroll
            for (int nt = 0; nt < 8; nt++) {
                int c = wn * 64 + nt * 8 + (lane >> 2);
                b[nt][0] = __float_as_uint(Bs[kk + (lane & 3)][c]);
                b[nt][1] = __float_as_uint(Bs[kk + 4 + (lane & 3)][c]);
            }
#pragma unroll
            for (int mt = 0; mt < 2; mt++)
#pragma unroll
                for (int nt = 0; nt < 8; nt++)
                    MMA_TF32(acc[mt][nt], a[mt], b[nt]);
        }
        __syncthreads();
    }

    // epilogue
#pragma unroll
    for (int mt = 0; mt < 2; mt++) {
        int r0 = mBase + wm * 32 + mt * 16 + (lane >> 2);
#pragma unroll
        for (int nt = 0; nt < 8; nt++) {
            int c0 = nBase + wn * 64 + nt * 8 + 2 * (lane & 3);
            float2 b2 = *(const float2*)(bias + c0);
            float2 o0 = make_float2(acc[mt][nt][0] + b2.x, acc[mt][nt][1] + b2.y);
            float2 o1 = make_float2(acc[mt][nt][2] + b2.x, acc[mt][nt][3] + b2.y);
            *(float2*)(C + (size_t)r0 * N + c0) = o0;
            *(float2*)(C + (size_t)(r0 + 8) * N + c0) = o1;
        }
    }
}

// ---------------- flash attention with tf32 MMA ----------------------------
// grid (S/64, B*H); 256 threads = 8 warps (4 along q-rows x 2 along cols).
// Q fragments live in registers across all 32 key tiles.
__global__ void __launch_bounds__(256)
attn_tf32(const float* __restrict__ Q, const float* __restrict__ K,
          const float* __restrict__ V, float* __restrict__ O) {
    extern __shared__ float sm[];
    float* Ks    = sm;                 // [64][72]  (key, d)
    float* Vs    = sm + 64 * 72;       // [64][72]  (key, d)
    float* Ps    = sm + 2 * 64 * 72;   // [64][72]  scores -> probs (tf32)
    float* alpha = sm + 3 * 64 * 72;   // [64]
    float* linv  = alpha + 64;         // [64]

    int tid = threadIdx.x, lane = tid & 31, wid = tid >> 5;
    int wm = wid & 3, wn = wid >> 2;
    int bh = blockIdx.y, b = bh >> 4, h = bh & 15;
    int qbase = blockIdx.x * 64;

    const float* Qg = Q + ((size_t)(b * S + qbase)) * D + h * DH;
    const float* Kg = K + ((size_t)(b * S)) * D + h * DH;
    const float* Vg = V + ((size_t)(b * S)) * D + h * DH;

    // Q fragments (pre-scaled by 1/sqrt(DH)=0.125), 8 k-steps over DH
    uint32_t qf[8][4];
    {
        int r0 = wm * 16 + (lane >> 2);
#pragma unroll
        for (int ks = 0; ks < 8; ks++) {
            int d0 = ks * 8 + (lane & 3);
            qf[ks][0] = __float_as_uint(cvt_tf32f(Qg[(size_t)r0 * D + d0] * 0.125f));
            qf[ks][1] = __float_as_uint(cvt_tf32f(Qg[(size_t)(r0 + 8) * D + d0] * 0.125f));
            qf[ks][2] = __float_as_uint(cvt_tf32f(Qg[(size_t)r0 * D + d0 + 4] * 0.125f));
            qf[ks][3] = __float_as_uint(cvt_tf32f(Qg[(size_t)(r0 + 8) * D + d0 + 4] * 0.125f));
        }
    }

    // softmax state: this thread owns row (wid*8 + lane>>2), chunk (lane&3)
    float m_prev = -1e30f, lsum = 0.f;
    float o[4][4] = {};   // PV accum, 4 d-tiles of n8

    for (int kt = 0; kt < S / 64; kt++) {
        __syncthreads();   // previous PV reads of Vs/Ps/alpha complete
        const float* Kt = Kg + (size_t)kt * 64 * D;
        const float* Vt = Vg + (size_t)kt * 64 * D;
#pragma unroll
        for (int i = 0; i < 4; i++) {
            int idx = tid + i * 256;
            int r = idx >> 4, c = (idx & 15) << 2;
            float4 kv = *(const float4*)(Kt + (size_t)r * D + c);
            Ks[r * 72 + c + 0] = cvt_tf32f(kv.x);
            Ks[r * 72 + c + 1] = cvt_tf32f(kv.y);
            Ks[r * 72 + c + 2] = cvt_tf32f(kv.z);
            Ks[r * 72 + c + 3] = cvt_tf32f(kv.w);
            float4 vv = *(const float4*)(Vt + (size_t)r * D + c);
            Vs[r * 72 + c + 0] = cvt_tf32f(vv.x);
            Vs[r * 72 + c + 1] = cvt_tf32f(vv.y);
            Vs[r * 72 + c + 2] = cvt_tf32f(vv.z);
            Vs[r * 72 + c + 3] = cvt_tf32f(vv.w);
        }
        __syncthreads();

        // --- QK^T: warp computes rows wm*16..+16, keys wn*32..+32 ---
        float sacc[4][4] = {};
#pragma unroll
        for (int ks = 0; ks < 8; ks++) {
            uint32_t bf[4][2];
#pragma unroll
            for (int nt = 0; nt < 4; nt++) {
                int key = wn * 32 + nt * 8 + (lane >> 2);
                bf[nt][0] = __float_as_uint(Ks[key * 72 + ks * 8 + (lane & 3)]);
                bf[nt][1] = __float_as_uint(Ks[key * 72 + ks * 8 + 4 + (lane & 3)]);
            }
#pragma unroll
            for (int nt = 0; nt < 4; nt++)
                MMA_TF32(sacc[nt], qf[ks], bf[nt]);
        }
        // stage scores to smem
        {
            int r0 = wm * 16 + (lane >> 2);
#pragma unroll
            for (int nt = 0; nt < 4; nt++) {
                int c0 = wn * 32 + nt * 8 + 2 * (lane & 3);
                *(float2*)&Ps[r0 * 72 + c0] = make_float2(sacc[nt][0], sacc[nt][1]);
                *(float2*)&Ps[(r0 + 8) * 72 + c0] = make_float2(sacc[nt][2], sacc[nt][3]);
            }
        }
        __syncthreads();

        // --- online softmax: 4 lanes per row, 16 cols each ---
        {
            int sr = wid * 8 + (lane >> 2);
            float* prow = &Ps[sr * 72 + (lane & 3) * 16];
            float4 x0 = *(float4*)(prow);
            float4 x1 = *(float4*)(prow + 4);
            float4 x2 = *(float4*)(prow + 8);
            float4 x3 = *(float4*)(prow + 12);
            float mx = fmaxf(fmaxf(fmaxf(x0.x, x0.y), fmaxf(x0.z, x0.w)),
                      fmaxf(fmaxf(fmaxf(x1.x, x1.y), fmaxf(x1.z, x1.w)),
                      fmaxf(fmaxf(fmaxf(x2.x, x2.y), fmaxf(x2.z, x2.w)),
                            fmaxf(fmaxf(x3.x, x3.y), fmaxf(x3.z, x3.w)))));
            mx = fmaxf(mx, __shfl_xor_sync(0xffffffffu, mx, 1));
            mx = fmaxf(mx, __shfl_xor_sync(0xffffffffu, mx, 2));
            float mnew = fmaxf(m_prev, mx);
            float al = __expf(m_prev - mnew);
            float rs = 0.f;
            float e[16];
            e[0]=__expf(x0.x-mnew); e[1]=__expf(x0.y-mnew); e[2]=__expf(x0.z-mnew); e[3]=__expf(x0.w-mnew);
            e[4]=__expf(x1.x-mnew); e[5]=__expf(x1.y-mnew); e[6]=__expf(x1.z-mnew); e[7]=__expf(x1.w-mnew);
            e[8]=__expf(x2.x-mnew); e[9]=__expf(x2.y-mnew); e[10]=__expf(x2.z-mnew); e[11]=__expf(x2.w-mnew);
            e[12]=__expf(x3.x-mnew); e[13]=__expf(x3.y-mnew); e[14]=__expf(x3.z-mnew); e[15]=__expf(x3.w-mnew);
#pragma unroll
            for (int j = 0; j < 16; j++) { rs += e[j]; prow[j] = cvt_tf32f(e[j]); }
            rs += __shfl_xor_sync(0xffffffffu, rs, 1);
            rs += __shfl_xor_sync(0xffffffffu, rs, 2);
            lsum = lsum * al + rs;
            m_prev = mnew;
            if ((lane & 3) == 0) alpha[sr] = al;
        }
        __syncthreads();

        // --- PV: warp computes rows wm*16..+16, d-cols wn*32..+32 ---
        {
            int r0 = wm * 16 + (lane >> 2);
            float al_lo = alpha[r0], al_hi = alpha[r0 + 8];
#pragma unroll
            for (int nt = 0; nt < 4; nt++) {
                o[nt][0] *= al_lo; o[nt][1] *= al_lo;
                o[nt][2] *= al_hi; o[nt][3] *= al_hi;
            }
#pragma unroll
            for (int ks = 0; ks < 8; ks++) {
                uint32_t af[4];
                int kc = ks * 8 + (lane & 3);
                af[0] = __float_as_uint(Ps[r0 * 72 + kc]);
                af[1] = __float_as_uint(Ps[(r0 + 8) * 72 + kc]);
                af[2] = __float_as_uint(Ps[r0 * 72 + kc + 4]);
                af[3] = __float_as_uint(Ps[(r0 + 8) * 72 + kc + 4]);
#pragma unroll
                for (int nt = 0; nt < 4; nt++) {
                    uint32_t bf[2];
                    int d0 = wn * 32 + nt * 8 + (lane >> 2);
                    bf[0] = __float_as_uint(Vs[(ks * 8 + (lane & 3)) * 72 + d0]);
                    bf[1] = __float_as_uint(Vs[(ks * 8 + 4 + (lane & 3)) * 72 + d0]);
                    MMA_TF32(o[nt], af, bf);
                }
            }
        }
    }

    // finalize: 1/l per row
    {
        int sr = wid * 8 + (lane >> 2);
        if ((lane & 3) == 0) linv[sr] = 1.0f / lsum;
    }
    __syncthreads();
    {
        int r0 = wm * 16 + (lane >> 2);
        float il_lo = linv[r0], il_hi = linv[r0 + 8];
        float* Og = O + ((size_t)(b * S + qbase)) * D + h * DH;
#pragma unroll
        for (int nt = 0; nt < 4; nt++) {
            int c0 = wn * 32 + nt * 8 + 2 * (lane & 3);
            *(float2*)(Og + (size_t)r0 * D + c0) =
                make_float2(o[nt][0] * il_lo, o[nt][1] * il_lo);
            *(float2*)(Og + (size_t)(r0 + 8) * D + c0) =
                make_float2(o[nt][2] * il_hi, o[nt][3] * il_hi);
        }
    }
}

// ---------------- launch ----------------------------------------------------
extern "C" void kernel_launch(void* const* d_in, const int* in_sizes, int n_in,
                              void* d_out, int out_size) {
    const float* x     = (const float*)d_in[0];
    const float* gamma = (const float*)d_in[1];
    const float* beta  = (const float*)d_in[2];
    const float* wq    = (const float*)d_in[3];
    const float* bq    = (const float*)d_in[4];
    const float* wk    = (const float*)d_in[5];
    const float* bk    = (const float*)d_in[6];
    const float* wv    = (const float*)d_in[7];
    const float* bv    = (const float*)d_in[8];
    const float* wo    = (const float*)d_in[9];
    const float* bo    = (const float*)d_in[10];
    float* out = (float*)d_out;

    float *xn, *q, *k, *v, *att;
    cudaGetSymbolAddress((void**)&xn,  g_xn);
    cudaGetSymbolAddress((void**)&q,   g_q);
    cudaGetSymbolAddress((void**)&k,   g_k);
    cudaGetSymbolAddress((void**)&v,   g_v);
    cudaGetSymbolAddress((void**)&att, g_att);

    // 1. LayerNorm
    ln_kernel<<<ROWS, 256>>>(x, gamma, beta, xn);

    // 2-4. Q/K/V projections (tf32 tensor cores)
    dim3 ggrid(D / 128, ROWS / 128);   // (8, 32)
    gemm_tf32<<<ggrid, 256>>>(xn, wq, bq, q, D, D);
    gemm_tf32<<<ggrid, 256>>>(xn, wk, bk, k, D, D);
    gemm_tf32<<<ggrid, 256>>>(xn, wv, bv, v, D, D);

    // 5. attention (tf32 tensor cores)
    int smem = (3 * 64 * 72 + 128) * (int)sizeof(float);  // 55808 B
    cudaFuncSetAttribute(attn_tf32,
                         cudaFuncAttributeMaxDynamicSharedMemorySize, smem);
    dim3 agrid(S / 64, B * H);
    attn_tf32<<<agrid, 256, smem>>>(q, k, v, att);

    // 6. output projection
    gemm_tf32<<<ggrid, 256>>>(att, wo, bo, out, D, D);
}

// round 3
// speedup vs baseline: 3.5114x; 1.2309x over previous
#include <cuda_runtime.h>
#include <math.h>
#include <stdint.h>

// Problem constants
#define B   2
#define S   2048
#define D   1024
#define H   16
#define DH  64
#define ROWS (B*S)           // 4096
#define EPS 1e-5f

// ---------------- scratch (device globals) ---------------------------------
__device__ float g_xn [ROWS * D];
__device__ float g_q  [ROWS * D];
__device__ float g_k  [ROWS * D];
__device__ float g_v  [ROWS * D];
__device__ float g_att[ROWS * D];
__device__ float g_wq [D * D];
__device__ float g_wk [D * D];
__device__ float g_wv [D * D];
__device__ float g_wo [D * D];

// ---------------- helpers ---------------------------------------------------
__device__ __forceinline__ float cvt_tf32f(float x) {
    uint32_t u;
    asm("cvt.rna.tf32.f32 %0, %1;" : "=r"(u) : "f"(x));
    return __uint_as_float(u);
}

#define MMA_TF32(c, a, b)                                                     \
    asm volatile(                                                             \
        "mma.sync.aligned.m16n8k8.row.col.f32.tf32.tf32.f32 "                 \
        "{%0,%1,%2,%3},{%4,%5,%6,%7},{%8,%9},{%0,%1,%2,%3};"                  \
        : "+f"((c)[0]), "+f"((c)[1]), "+f"((c)[2]), "+f"((c)[3])              \
        : "r"((a)[0]), "r"((a)[1]), "r"((a)[2]), "r"((a)[3]),                 \
          "r"((b)[0]), "r"((b)[1]))

__device__ __forceinline__ uint32_t smaddr(const void* p) {
    return (uint32_t)__cvta_generic_to_shared(p);
}
#define CP_ASYNC16(dst, src)                                                  \
    asm volatile("cp.async.cg.shared.global [%0], [%1], 16;\n"                \
                 :: "r"(dst), "l"(src))
#define CP_COMMIT() asm volatile("cp.async.commit_group;\n")
#define CP_WAIT1()  asm volatile("cp.async.wait_group 1;\n")
#define CP_WAIT0()  asm volatile("cp.async.wait_group 0;\n")

// ---------------- weight pre-rounding (tf32) --------------------------------
__global__ void round_w(const float* __restrict__ a, const float* __restrict__ b,
                        const float* __restrict__ c, const float* __restrict__ d,
                        float* __restrict__ oa, float* __restrict__ ob,
                        float* __restrict__ oc, float* __restrict__ od) {
    int i = (blockIdx.x * 256 + threadIdx.x) * 4;
    const float* src = blockIdx.y == 0 ? a : blockIdx.y == 1 ? b
                     : blockIdx.y == 2 ? c : d;
    float* dst = blockIdx.y == 0 ? oa : blockIdx.y == 1 ? ob
               : blockIdx.y == 2 ? oc : od;
    float4 v = *(const float4*)(src + i);
    v.x = cvt_tf32f(v.x); v.y = cvt_tf32f(v.y);
    v.z = cvt_tf32f(v.z); v.w = cvt_tf32f(v.w);
    *(float4*)(dst + i) = v;
}

// ---------------- LayerNorm (writes tf32-rounded output) --------------------
__global__ void ln_kernel(const float* __restrict__ x,
                          const float* __restrict__ gamma,
                          const float* __restrict__ beta,
                          float* __restrict__ out) {
    int row = blockIdx.x;
    const float* xr = x + (size_t)row * D;
    float* orow = out + (size_t)row * D;

    float vals[4];
    float sum = 0.f, sq = 0.f;
#pragma unroll
    for (int i = 0; i < 4; i++) {
        float v = xr[threadIdx.x + i * 256];
        vals[i] = v;
        sum += v; sq += v * v;
    }
#pragma unroll
    for (int o = 16; o >= 1; o >>= 1) {
        sum += __shfl_xor_sync(0xffffffffu, sum, o);
        sq  += __shfl_xor_sync(0xffffffffu, sq , o);
    }
    __shared__ float ssum[8], ssq[8];
    int warp = threadIdx.x >> 5, lane = threadIdx.x & 31;
    if (lane == 0) { ssum[warp] = sum; ssq[warp] = sq; }
    __syncthreads();
    float ts = 0.f, tq = 0.f;
#pragma unroll
    for (int w = 0; w < 8; w++) { ts += ssum[w]; tq += ssq[w]; }
    float mu  = ts * (1.0f / D);
    float var = tq * (1.0f / D) - mu * mu;
    float rstd = rsqrtf(var + EPS);
#pragma unroll
    for (int i = 0; i < 4; i++) {
        int c = threadIdx.x + i * 256;
        orow[c] = cvt_tf32f((vals[i] - mu) * rstd * gamma[c] + beta[c]);
    }
}

// ---------------- tf32 GEMM, cp.async 2-stage pipeline ----------------------
// Block tile 128x128, BK=32, 256 threads = 8 warps (4 M x 2 N), warp 32x64.
// blockIdx.z selects (W,bias,C) triple. Inputs must be pre-rounded to tf32.
template <bool RND>
__global__ void __launch_bounds__(256)
gemm_tc(const float* __restrict__ A,
        const float* __restrict__ W0, const float* __restrict__ W1,
        const float* __restrict__ W2,
        const float* __restrict__ b0, const float* __restrict__ b1,
        const float* __restrict__ b2,
        float* __restrict__ C0, float* __restrict__ C1, float* __restrict__ C2,
        int K, int N) {
    extern __shared__ float sm[];
    float* AS = sm;            // [2][128][36]
    float* BS = sm + 9216;     // [2][32][136]

    int z = blockIdx.z;
    const float* W = z == 0 ? W0 : z == 1 ? W1 : W2;
    const float* bias = z == 0 ? b0 : z == 1 ? b1 : b2;
    float* C = z == 0 ? C0 : z == 1 ? C1 : C2;

    int tid = threadIdx.x, lane = tid & 31, wid = tid >> 5;
    int wm = wid & 3, wn = wid >> 2;
    int mBase = blockIdx.y * 128, nBase = blockIdx.x * 128;

    float acc[2][8][4] = {};

    // prologue load
    {
        float* As = AS; float* Bs = BS;
#pragma unroll
        for (int i = 0; i < 4; i++) {
            int id = tid + i * 256;
            int r = id >> 3, c4 = (id & 7) << 2;
            CP_ASYNC16(smaddr(As + r * 36 + c4),
                       A + (size_t)(mBase + r) * K + c4);
        }
#pragma unroll
        for (int i = 0; i < 4; i++) {
            int id = tid + i * 256;
            int r = id >> 5, c4 = (id & 31) << 2;
            CP_ASYNC16(smaddr(Bs + r * 136 + c4),
                       W + (size_t)r * N + nBase + c4);
        }
        CP_COMMIT();
    }

    int NT = K / 32;
    for (int kt = 0; kt < NT; kt++) {
        if (kt + 1 < NT) {
            int k0 = (kt + 1) * 32;
            float* As = AS + ((kt + 1) & 1) * 4608;   // 128*36
            float* Bs = BS + ((kt + 1) & 1) * 4352;   // 32*136
#pragma unroll
            for (int i = 0; i < 4; i++) {
                int id = tid + i * 256;
                int r = id >> 3, c4 = (id & 7) << 2;
                CP_ASYNC16(smaddr(As + r * 36 + c4),
                           A + (size_t)(mBase + r) * K + k0 + c4);
            }
#pragma unroll
            for (int i = 0; i < 4; i++) {
                int id = tid + i * 256;
                int r = id >> 5, c4 = (id & 31) << 2;
                CP_ASYNC16(smaddr(Bs + r * 136 + c4),
                           W + (size_t)(k0 + r) * N + nBase + c4);
            }
            CP_COMMIT();
            CP_WAIT1();
        } else {
            CP_WAIT0();
        }
        __syncthreads();

        float* As = AS + (kt & 1) * 4608;
        float* Bs = BS + (kt & 1) * 4352;
#pragma unroll
        for (int ks = 0; ks < 4; ks++) {
            int kk = ks * 8;
            uint32_t a[2][4], b[8][2];
#pragma unroll
            for (int mt = 0; mt < 2; mt++) {
                int r = wm * 32 + mt * 16 + (lane >> 2);
                int kc = kk + (lane & 3);
                a[mt][0] = __float_as_uint(As[r * 36 + kc]);
                a[mt][1] = __float_as_uint(As[(r + 8) * 36 + kc]);
                a[mt][2] = __float_as_uint(As[r * 36 + kc + 4]);
                a[mt][3] = __float_as_uint(As[(r + 8) * 36 + kc + 4]);
            }
#pragma unroll
            for (int nt = 0; nt < 8; nt++) {
                int c = wn * 64 + nt * 8 + (lane >> 2);
                b[nt][0] = __float_as_uint(Bs[(kk + (lane & 3)) * 136 + c]);
                b[nt][1] = __float_as_uint(Bs[(kk + 4 + (lane & 3)) * 136 + c]);
            }
#pragma unroll
            for (int mt = 0; mt < 2; mt++)
#pragma unroll
                for (int nt = 0; nt < 8; nt++)
                    MMA_TF32(acc[mt][nt], a[mt], b[nt]);
        }
        __syncthreads();
    }

    // epilogue
#pragma unroll
    for (int mt = 0; mt < 2; mt++) {
        int r0 = mBase + wm * 32 + mt * 16 + (lane >> 2);
#pragma unroll
        for (int nt = 0; nt < 8; nt++) {
            int c0 = nBase + wn * 64 + nt * 8 + 2 * (lane & 3);
            float2 b2 = *(const float2*)(bias + c0);
            float2 o0, o1;
            if (RND) {
                o0 = make_float2(cvt_tf32f(acc[mt][nt][0] + b2.x),
                                 cvt_tf32f(acc[mt][nt][1] + b2.y));
                o1 = make_float2(cvt_tf32f(acc[mt][nt][2] + b2.x),
                                 cvt_tf32f(acc[mt][nt][3] + b2.y));
            } else {
                o0 = make_float2(acc[mt][nt][0] + b2.x, acc[mt][nt][1] + b2.y);
                o1 = make_float2(acc[mt][nt][2] + b2.x, acc[mt][nt][3] + b2.y);
            }
            *(float2*)(C + (size_t)r0 * N + c0) = o0;
            *(float2*)(C + (size_t)(r0 + 8) * N + c0) = o1;
        }
    }
}

// ---------------- flash attention, warp-owned rows, cp.async K/V ------------
// grid (S/128, B*H); 256 thr = 8 warps; warp w owns q-rows w*16..w*16+15 and
// the full 64-key tile -> softmax is warp-local (no block syncs for P).
// Q/K/V are pre-rounded tf32. Output written tf32-rounded (feeds final GEMM).
__global__ void __launch_bounds__(256, 2)
attn_tc(const float* __restrict__ Q, const float* __restrict__ K,
        const float* __restrict__ V, float* __restrict__ O) {
    extern __shared__ float sm[];
    float* KsB = sm;            // [2][64][68]
    float* VsB = sm + 8704;     // [2][64][72]
    // per-warp P: [16][68]
    int tid = threadIdx.x, lane = tid & 31, wid = tid >> 5;
    float* Pw = sm + 17920 + wid * (16 * 68);

    int q = lane >> 2, j = lane & 3;
    int bh = blockIdx.y, b = bh >> 4, h = bh & 15;
    int qbase = blockIdx.x * 128;

    const float* Kg = K + (size_t)(b * S) * D + h * DH;
    const float* Vg = V + (size_t)(b * S) * D + h * DH;
    const float* Qg = Q + (size_t)(b * S + qbase + wid * 16) * D + h * DH;

    // Q fragments, scaled by 1/8 (exact in tf32)
    uint32_t qf[8][4];
#pragma unroll
    for (int ks = 0; ks < 8; ks++) {
        int d0 = ks * 8 + j;
        qf[ks][0] = __float_as_uint(Qg[(size_t)q * D + d0] * 0.125f);
        qf[ks][1] = __float_as_uint(Qg[(size_t)(q + 8) * D + d0] * 0.125f);
        qf[ks][2] = __float_as_uint(Qg[(size_t)q * D + d0 + 4] * 0.125f);
        qf[ks][3] = __float_as_uint(Qg[(size_t)(q + 8) * D + d0 + 4] * 0.125f);
    }

    float o[8][4] = {};
    float mrow = -1e30f, lrow = 0.f;   // softmax state for row (lane>>1)

    // prologue: load tile 0
    {
#pragma unroll
        for (int i = 0; i < 4; i++) {
            int id = tid + i * 256;
            int r = id >> 4, c4 = (id & 15) << 2;
            CP_ASYNC16(smaddr(KsB + r * 68 + c4), Kg + (size_t)r * D + c4);
            CP_ASYNC16(smaddr(VsB + r * 72 + c4), Vg + (size_t)r * D + c4);
        }
        CP_COMMIT();
    }

    for (int kt = 0; kt < S / 64; kt++) {
        int st = kt & 1;
        if (kt + 1 < S / 64) {
            const float* Kt = Kg + (size_t)(kt + 1) * 64 * D;
            const float* Vt = Vg + (size_t)(kt + 1) * 64 * D;
            float* Kd = KsB + (st ^ 1) * 4352;
            float* Vd = VsB + (st ^ 1) * 4608;
#pragma unroll
            for (int i = 0; i < 4; i++) {
                int id = tid + i * 256;
                int r = id >> 4, c4 = (id & 15) << 2;
                CP_ASYNC16(smaddr(Kd + r * 68 + c4), Kt + (size_t)r * D + c4);
                CP_ASYNC16(smaddr(Vd + r * 72 + c4), Vt + (size_t)r * D + c4);
            }
            CP_COMMIT();
            CP_WAIT1();
        } else {
            CP_WAIT0();
        }
        __syncthreads();

        const float* Ks = KsB + st * 4352;
        const float* Vs = VsB + st * 4608;

        // ---- QK^T: 2 n-tiles in flight, stage raw scores to Pw ----
#pragma unroll
        for (int pr = 0; pr < 4; pr++) {
            float s0[4] = {}, s1[4] = {};
            int key0 = pr * 16 + q;
#pragma unroll
            for (int ks = 0; ks < 8; ks++) {
                int kc = ks * 8 + j;
                uint32_t bf0[2], bf1[2];
                bf0[0] = __float_as_uint(Ks[key0 * 68 + kc]);
                bf0[1] = __float_as_uint(Ks[key0 * 68 + kc + 4]);
                bf1[0] = __float_as_uint(Ks[(key0 + 8) * 68 + kc]);
                bf1[1] = __float_as_uint(Ks[(key0 + 8) * 68 + kc + 4]);
                MMA_TF32(s0, qf[ks], bf0);
                MMA_TF32(s1, qf[ks], bf1);
            }
            int c0 = pr * 16 + 2 * j;
            *(float2*)&Pw[q * 68 + c0]           = make_float2(s0[0], s0[1]);
            *(float2*)&Pw[(q + 8) * 68 + c0]     = make_float2(s0[2], s0[3]);
            *(float2*)&Pw[q * 68 + c0 + 8]       = make_float2(s1[0], s1[1]);
            *(float2*)&Pw[(q + 8) * 68 + c0 + 8] = make_float2(s1[2], s1[3]);
        }
        __syncwarp();

        // ---- warp-local online softmax: row = lane>>1, cols (lane&1)*32.. ----
        float al;
        {
            int r = lane >> 1, hf = lane & 1;
            float* prow = &Pw[r * 68 + hf * 32];
            float x[32];
#pragma unroll
            for (int i = 0; i < 8; i++) {
                float4 v = *(float4*)(prow + i * 4);
                x[4*i] = v.x; x[4*i+1] = v.y; x[4*i+2] = v.z; x[4*i+3] = v.w;
            }
            float mx = x[0];
#pragma unroll
            for (int i = 1; i < 32; i++) mx = fmaxf(mx, x[i]);
            mx = fmaxf(mx, __shfl_xor_sync(0xffffffffu, mx, 1));
            float mnew = fmaxf(mrow, mx);
            al = __expf(mrow - mnew);
            float rs = 0.f;
#pragma unroll
            for (int i = 0; i < 32; i++) { x[i] = __expf(x[i] - mnew); rs += x[i]; }
            rs += __shfl_xor_sync(0xffffffffu, rs, 1);
            lrow = lrow * al + rs;
            mrow = mnew;
#pragma unroll
            for (int i = 0; i < 32; i++) prow[i] = cvt_tf32f(x[i]);
        }
        __syncwarp();

        // rescale O by alpha of rows q, q+8 (fetched from softmax lanes)
        float al_lo = __shfl_sync(0xffffffffu, al, 2 * q);
        float al_hi = __shfl_sync(0xffffffffu, al, 2 * q + 16);
#pragma unroll
        for (int dt = 0; dt < 8; dt++) {
            o[dt][0] *= al_lo; o[dt][1] *= al_lo;
            o[dt][2] *= al_hi; o[dt][3] *= al_hi;
        }

        // ---- PV: O[16,64] += P[16,64] @ V[64,64] ----
#pragma unroll
        for (int ks = 0; ks < 8; ks++) {
            uint32_t af[4];
            int kc = ks * 8 + j;
            af[0] = __float_as_uint(Pw[q * 68 + kc]);
            af[1] = __float_as_uint(Pw[(q + 8) * 68 + kc]);
            af[2] = __float_as_uint(Pw[q * 68 + kc + 4]);
            af[3] = __float_as_uint(Pw[(q + 8) * 68 + kc + 4]);
#pragma unroll
            for (int dt = 0; dt < 8; dt++) {
                uint32_t bf[2];
                int d0 = dt * 8 + q;
                bf[0] = __float_as_uint(Vs[(ks * 8 + j) * 72 + d0]);
                bf[1] = __float_as_uint(Vs[(ks * 8 + 4 + j) * 72 + d0]);
                MMA_TF32(o[dt], af, bf);
            }
        }
        __syncthreads();
    }

    // ---- epilogue: divide by l, write tf32-rounded ----
    float il = 1.0f / lrow;
    float il_lo = __shfl_sync(0xffffffffu, il, 2 * q);
    float il_hi = __shfl_sync(0xffffffffu, il, 2 * q + 16);
    float* Og = O + (size_t)(b * S + qbase + wid * 16) * D + h * DH;
#pragma unroll
    for (int dt = 0; dt < 8; dt++) {
        int c0 = dt * 8 + 2 * j;
        *(float2*)(Og + (size_t)q * D + c0) =
            make_float2(cvt_tf32f(o[dt][0] * il_lo), cvt_tf32f(o[dt][1] * il_lo));
        *(float2*)(Og + (size_t)(q + 8) * D + c0) =
            make_float2(cvt_tf32f(o[dt][2] * il_hi), cvt_tf32f(o[dt][3] * il_hi));
    }
}

// ---------------- launch ----------------------------------------------------
extern "C" void kernel_launch(void* const* d_in, const int* in_sizes, int n_in,
                              void* d_out, int out_size) {
    const float* x     = (const float*)d_in[0];
    const float* gamma = (const float*)d_in[1];
    const float* beta  = (const float*)d_in[2];
    const float* wq    = (const float*)d_in[3];
    const float* bq    = (const float*)d_in[4];
    const float* wk    = (const float*)d_in[5];
    const float* bk    = (const float*)d_in[6];
    const float* wv    = (const float*)d_in[7];
    const float* bv    = (const float*)d_in[8];
    const float* wo    = (const float*)d_in[9];
    const float* bo    = (const float*)d_in[10];
    float* out = (float*)d_out;

    float *xn, *q, *k, *v, *att, *rwq, *rwk, *rwv, *rwo;
    cudaGetSymbolAddress((void**)&xn,  g_xn);
    cudaGetSymbolAddress((void**)&q,   g_q);
    cudaGetSymbolAddress((void**)&k,   g_k);
    cudaGetSymbolAddress((void**)&v,   g_v);
    cudaGetSymbolAddress((void**)&att, g_att);
    cudaGetSymbolAddress((void**)&rwq, g_wq);
    cudaGetSymbolAddress((void**)&rwk, g_wk);
    cudaGetSymbolAddress((void**)&rwv, g_wv);
    cudaGetSymbolAddress((void**)&rwo, g_wo);

    int gemm_smem = 17920 * (int)sizeof(float);       // 71680 B
    int attn_smem = (17920 + 8 * 16 * 68) * (int)sizeof(float);  // 106496 B
    cudaFuncSetAttribute(gemm_tc<true>,
                         cudaFuncAttributeMaxDynamicSharedMemorySize, gemm_smem);
    cudaFuncSetAttribute(gemm_tc<false>,
                         cudaFuncAttributeMaxDynamicSharedMemorySize, gemm_smem);
    cudaFuncSetAttribute(attn_tc,
                         cudaFuncAttributeMaxDynamicSharedMemorySize, attn_smem);

    // 0. round weights to tf32 once per call
    round_w<<<dim3(D * D / 1024, 4), 256>>>(wq, wk, wv, wo, rwq, rwk, rwv, rwo);

    // 1. LayerNorm (tf32-rounded output)
    ln_kernel<<<ROWS, 256>>>(x, gamma, beta, xn);

    // 2. fused Q/K/V projection (rounded outputs)
    dim3 ggrid(D / 128, ROWS / 128, 3);
    gemm_tc<true><<<ggrid, 256, gemm_smem>>>(xn, rwq, rwk, rwv, bq, bk, bv,
                                             q, k, v, D, D);

    // 3. attention (rounded output)
    dim3 agrid(S / 128, B * H);
    attn_tc<<<agrid, 256, attn_smem>>>(q, k, v, att);

    // 4. output projection (fp32 output)
    dim3 ogrid(D / 128, ROWS / 128, 1);
    gemm_tc<false><<<ogrid, 256, gemm_smem>>>(att, rwo, rwo, rwo, bo, bo, bo,
                                              out, out, out, D, D);
}

// round 4
// speedup vs baseline: 3.9253x; 1.1179x over previous
#include <cuda_runtime.h>
#include <math.h>
#include <stdint.h>

// Problem constants
#define B   2
#define S   2048
#define D   1024
#define H   16
#define DH  64
#define ROWS (B*S)           // 4096
#define EPS 1e-5f

// ---------------- scratch (device globals) ---------------------------------
__device__ float g_xn [ROWS * D];
__device__ float g_q  [ROWS * D];
__device__ float g_k  [ROWS * D];
__device__ float g_v  [ROWS * D];
__device__ float g_att[ROWS * D];
__device__ float g_wq [D * D];
__device__ float g_wk [D * D];
__device__ float g_wv [D * D];
__device__ float g_wo [D * D];

// ---------------- helpers ---------------------------------------------------
__device__ __forceinline__ float cvt_tf32f(float x) {
    uint32_t u;
    asm("cvt.rna.tf32.f32 %0, %1;" : "=r"(u) : "f"(x));
    return __uint_as_float(u);
}

#define MMA_TF32(c, a, b)                                                     \
    asm volatile(                                                             \
        "mma.sync.aligned.m16n8k8.row.col.f32.tf32.tf32.f32 "                 \
        "{%0,%1,%2,%3},{%4,%5,%6,%7},{%8,%9},{%0,%1,%2,%3};"                  \
        : "+f"((c)[0]), "+f"((c)[1]), "+f"((c)[2]), "+f"((c)[3])              \
        : "r"((a)[0]), "r"((a)[1]), "r"((a)[2]), "r"((a)[3]),                 \
          "r"((b)[0]), "r"((b)[1]))

__device__ __forceinline__ uint32_t smaddr(const void* p) {
    return (uint32_t)__cvta_generic_to_shared(p);
}
#define CP_ASYNC16(dst, src)                                                  \
    asm volatile("cp.async.cg.shared.global [%0], [%1], 16;\n"                \
                 :: "r"(dst), "l"(src))
#define CP_COMMIT() asm volatile("cp.async.commit_group;\n")
#define CP_WAIT1()  asm volatile("cp.async.wait_group 1;\n")
#define CP_WAIT0()  asm volatile("cp.async.wait_group 0;\n")

// ---------------- weight pre-rounding (tf32) --------------------------------
__global__ void round_w(const float* __restrict__ a, const float* __restrict__ b,
                        const float* __restrict__ c, const float* __restrict__ d,
                        float* __restrict__ oa, float* __restrict__ ob,
                        float* __restrict__ oc, float* __restrict__ od) {
    int i = (blockIdx.x * 256 + threadIdx.x) * 4;
    const float* src = blockIdx.y == 0 ? a : blockIdx.y == 1 ? b
                     : blockIdx.y == 2 ? c : d;
    float* dst = blockIdx.y == 0 ? oa : blockIdx.y == 1 ? ob
               : blockIdx.y == 2 ? oc : od;
    float4 v = *(const float4*)(src + i);
    v.x = cvt_tf32f(v.x); v.y = cvt_tf32f(v.y);
    v.z = cvt_tf32f(v.z); v.w = cvt_tf32f(v.w);
    *(float4*)(dst + i) = v;
}

// ---------------- LayerNorm (writes tf32-rounded output) --------------------
__global__ void ln_kernel(const float* __restrict__ x,
                          const float* __restrict__ gamma,
                          const float* __restrict__ beta,
                          float* __restrict__ out) {
    int row = blockIdx.x;
    const float* xr = x + (size_t)row * D;
    float* orow = out + (size_t)row * D;

    float vals[4];
    float sum = 0.f, sq = 0.f;
#pragma unroll
    for (int i = 0; i < 4; i++) {
        float v = xr[threadIdx.x + i * 256];
        vals[i] = v;
        sum += v; sq += v * v;
    }
#pragma unroll
    for (int o = 16; o >= 1; o >>= 1) {
        sum += __shfl_xor_sync(0xffffffffu, sum, o);
        sq  += __shfl_xor_sync(0xffffffffu, sq , o);
    }
    __shared__ float ssum[8], ssq[8];
    int warp = threadIdx.x >> 5, lane = threadIdx.x & 31;
    if (lane == 0) { ssum[warp] = sum; ssq[warp] = sq; }
    __syncthreads();
    float ts = 0.f, tq = 0.f;
#pragma unroll
    for (int w = 0; w < 8; w++) { ts += ssum[w]; tq += ssq[w]; }
    float mu  = ts * (1.0f / D);
    float var = tq * (1.0f / D) - mu * mu;
    float rstd = rsqrtf(var + EPS);
#pragma unroll
    for (int i = 0; i < 4; i++) {
        int c = threadIdx.x + i * 256;
        orow[c] = cvt_tf32f((vals[i] - mu) * rstd * gamma[c] + beta[c]);
    }
}

// ---------------- tf32 GEMM, cp.async 3-stage ring, 1 sync/slab -------------
// Block tile 128x128, BK=32, 256 threads = 8 warps (4 M x 2 N), warp 32x64.
// blockIdx.z selects (W,bias,C) triple. Inputs pre-rounded tf32.
#define GST 8960   // floats per stage: 128*36 + 32*136

template <bool RND>
__global__ void __launch_bounds__(256)
gemm_tc(const float* __restrict__ A,
        const float* __restrict__ W0, const float* __restrict__ W1,
        const float* __restrict__ W2,
        const float* __restrict__ b0, const float* __restrict__ b1,
        const float* __restrict__ b2,
        float* __restrict__ C0, float* __restrict__ C1, float* __restrict__ C2,
        int K, int N) {
    extern __shared__ float sm[];

    int z = blockIdx.z;
    const float* W = z == 0 ? W0 : z == 1 ? W1 : W2;
    const float* bias = z == 0 ? b0 : z == 1 ? b1 : b2;
    float* C = z == 0 ? C0 : z == 1 ? C1 : C2;

    int tid = threadIdx.x, lane = tid & 31, wid = tid >> 5;
    int wm = wid & 3, wn = wid >> 2;
    int mBase = blockIdx.y * 128, nBase = blockIdx.x * 128;

    float acc[2][8][4] = {};

    // per-thread load coords
    int ra = tid >> 3, ca4 = (tid & 7) << 2;      // A: 128 rows x 32
    int rb = tid >> 5, cb4 = (tid & 31) << 2;     // B: 32 rows x 128

    auto issue = [&](int kt) {
        float* As = sm + (kt % 3) * GST;
        float* Bs = As + 4608;
        int k0 = kt * 32;
#pragma unroll
        for (int i = 0; i < 4; i++)
            CP_ASYNC16(smaddr(As + (ra + i * 32) * 36 + ca4),
                       A + (size_t)(mBase + ra + i * 32) * K + k0 + ca4);
#pragma unroll
        for (int i = 0; i < 4; i++)
            CP_ASYNC16(smaddr(Bs + (rb + i * 8) * 136 + cb4),
                       W + (size_t)(k0 + rb + i * 8) * N + nBase + cb4);
        CP_COMMIT();
    };

    int NT = K / 32;
    issue(0);
    if (NT > 1) issue(1);

    for (int kt = 0; kt < NT; kt++) {
        if (kt + 1 < NT) { CP_WAIT1(); } else { CP_WAIT0(); }
        __syncthreads();

        float* As = sm + (kt % 3) * GST;
        float* Bs = As + 4608;
#pragma unroll
        for (int ks = 0; ks < 4; ks++) {
            int kk = ks * 8;
            uint32_t a[2][4], b[8][2];
#pragma unroll
            for (int mt = 0; mt < 2; mt++) {
                int r = wm * 32 + mt * 16 + (lane >> 2);
                int kc = kk + (lane & 3);
                a[mt][0] = __float_as_uint(As[r * 36 + kc]);
                a[mt][1] = __float_as_uint(As[(r + 8) * 36 + kc]);
                a[mt][2] = __float_as_uint(As[r * 36 + kc + 4]);
                a[mt][3] = __float_as_uint(As[(r + 8) * 36 + kc + 4]);
            }
#pragma unroll
            for (int nt = 0; nt < 8; nt++) {
                int c = wn * 64 + nt * 8 + (lane >> 2);
                b[nt][0] = __float_as_uint(Bs[(kk + (lane & 3)) * 136 + c]);
                b[nt][1] = __float_as_uint(Bs[(kk + 4 + (lane & 3)) * 136 + c]);
            }
#pragma unroll
            for (int mt = 0; mt < 2; mt++)
#pragma unroll
                for (int nt = 0; nt < 8; nt++)
                    MMA_TF32(acc[mt][nt], a[mt], b[nt]);
        }

        if (kt + 2 < NT) issue(kt + 2);
    }

    // epilogue
#pragma unroll
    for (int mt = 0; mt < 2; mt++) {
        int r0 = mBase + wm * 32 + mt * 16 + (lane >> 2);
#pragma unroll
        for (int nt = 0; nt < 8; nt++) {
            int c0 = nBase + wn * 64 + nt * 8 + 2 * (lane & 3);
            float2 b2 = *(const float2*)(bias + c0);
            float2 o0, o1;
            if (RND) {
                o0 = make_float2(cvt_tf32f(acc[mt][nt][0] + b2.x),
                                 cvt_tf32f(acc[mt][nt][1] + b2.y));
                o1 = make_float2(cvt_tf32f(acc[mt][nt][2] + b2.x),
                                 cvt_tf32f(acc[mt][nt][3] + b2.y));
            } else {
                o0 = make_float2(acc[mt][nt][0] + b2.x, acc[mt][nt][1] + b2.y);
                o1 = make_float2(acc[mt][nt][2] + b2.x, acc[mt][nt][3] + b2.y);
            }
            *(float2*)(C + (size_t)r0 * N + c0) = o0;
            *(float2*)(C + (size_t)(r0 + 8) * N + c0) = o1;
        }
    }
}

// ---------------- flash attention: register softmax, shuffle P --------------
// grid (S/128, B*H); 256 thr = 8 warps; warp w owns q-rows w*16..w*16+15 and
// the full 64-key tile. P never touches smem: QK^T fragments are softmaxed in
// registers; PV A-fragments built by quad shuffles. 3-stage K/V cp.async ring,
// ONE __syncthreads per key tile.
#define AST 8960   // floats per stage: 64*68 (K) + 64*72 (V)

__global__ void __launch_bounds__(256, 2)
attn_tc(const float* __restrict__ Q, const float* __restrict__ K,
        const float* __restrict__ V, float* __restrict__ O) {
    extern __shared__ float sm[];

    int tid = threadIdx.x, lane = tid & 31, wid = tid >> 5;
    int q = lane >> 2, j = lane & 3;
    int bh = blockIdx.y, b = bh >> 4, h = bh & 15;
    int qbase = blockIdx.x * 128;

    const float* Kg = K + (size_t)(b * S) * D + h * DH;
    const float* Vg = V + (size_t)(b * S) * D + h * DH;
    const float* Qg = Q + (size_t)(b * S + qbase + wid * 16) * D + h * DH;

    // per-thread K/V load coords
    int rkv = tid >> 4, ckv = (tid & 15) << 2;

    auto issue = [&](int kt) {
        float* Ks = sm + (kt % 3) * AST;
        float* Vs = Ks + 4352;
        const float* Kt = Kg + (size_t)kt * 64 * D;
        const float* Vt = Vg + (size_t)kt * 64 * D;
#pragma unroll
        for (int i = 0; i < 4; i++) {
            int r = rkv + i * 16;
            CP_ASYNC16(smaddr(Ks + r * 68 + ckv), Kt + (size_t)r * D + ckv);
            CP_ASYNC16(smaddr(Vs + r * 72 + ckv), Vt + (size_t)r * D + ckv);
        }
        CP_COMMIT();
    };

    // Q fragments, scaled by 1/8 (exact in fp32/tf32)
    uint32_t qf[8][4];
#pragma unroll
    for (int ks = 0; ks < 8; ks++) {
        int d0 = ks * 8 + j;
        qf[ks][0] = __float_as_uint(Qg[(size_t)q * D + d0] * 0.125f);
        qf[ks][1] = __float_as_uint(Qg[(size_t)(q + 8) * D + d0] * 0.125f);
        qf[ks][2] = __float_as_uint(Qg[(size_t)q * D + d0 + 4] * 0.125f);
        qf[ks][3] = __float_as_uint(Qg[(size_t)(q + 8) * D + d0 + 4] * 0.125f);
    }

    float o[8][4] = {};
    float m0 = -1e30f, m1 = -1e30f, l0 = 0.f, l1 = 0.f;

    issue(0);
    issue(1);

    const int NKT = S / 64;
    for (int kt = 0; kt < NKT; kt++) {
        if (kt + 1 < NKT) { CP_WAIT1(); } else { CP_WAIT0(); }
        __syncthreads();

        const float* Ks = sm + (kt % 3) * AST;
        const float* Vs = Ks + 4352;

        // ---- QK^T into register fragments p[8][4] ----
        float p[8][4];
#pragma unroll
        for (int pr = 0; pr < 4; pr++) {
            float s0[4] = {}, s1[4] = {};
            int key0 = pr * 16 + q;
#pragma unroll
            for (int ks = 0; ks < 8; ks++) {
                int kc = ks * 8 + j;
                uint32_t bf0[2], bf1[2];
                bf0[0] = __float_as_uint(Ks[key0 * 68 + kc]);
                bf0[1] = __float_as_uint(Ks[key0 * 68 + kc + 4]);
                bf1[0] = __float_as_uint(Ks[(key0 + 8) * 68 + kc]);
                bf1[1] = __float_as_uint(Ks[(key0 + 8) * 68 + kc + 4]);
                MMA_TF32(s0, qf[ks], bf0);
                MMA_TF32(s1, qf[ks], bf1);
            }
#pragma unroll
            for (int u = 0; u < 4; u++) {
                p[2 * pr][u] = s0[u];
                p[2 * pr + 1][u] = s1[u];
            }
        }

        // ---- register online softmax (rows q and q+8) ----
        float mx0 = p[0][0], mx1 = p[0][2];
#pragma unroll
        for (int nt = 0; nt < 8; nt++) {
            mx0 = fmaxf(mx0, fmaxf(p[nt][0], p[nt][1]));
            mx1 = fmaxf(mx1, fmaxf(p[nt][2], p[nt][3]));
        }
        mx0 = fmaxf(mx0, __shfl_xor_sync(0xffffffffu, mx0, 1));
        mx0 = fmaxf(mx0, __shfl_xor_sync(0xffffffffu, mx0, 2));
        mx1 = fmaxf(mx1, __shfl_xor_sync(0xffffffffu, mx1, 1));
        mx1 = fmaxf(mx1, __shfl_xor_sync(0xffffffffu, mx1, 2));

        float mn0 = fmaxf(m0, mx0), mn1 = fmaxf(m1, mx1);
        float al0 = __expf(m0 - mn0), al1 = __expf(m1 - mn1);
        float rs0 = 0.f, rs1 = 0.f;
#pragma unroll
        for (int nt = 0; nt < 8; nt++) {
            float e0 = __expf(p[nt][0] - mn0);
            float e1 = __expf(p[nt][1] - mn0);
            float e2 = __expf(p[nt][2] - mn1);
            float e3 = __expf(p[nt][3] - mn1);
            rs0 += e0 + e1; rs1 += e2 + e3;
            p[nt][0] = cvt_tf32f(e0); p[nt][1] = cvt_tf32f(e1);
            p[nt][2] = cvt_tf32f(e2); p[nt][3] = cvt_tf32f(e3);
        }
        rs0 += __shfl_xor_sync(0xffffffffu, rs0, 1);
        rs0 += __shfl_xor_sync(0xffffffffu, rs0, 2);
        rs1 += __shfl_xor_sync(0xffffffffu, rs1, 1);
        rs1 += __shfl_xor_sync(0xffffffffu, rs1, 2);
        l0 = l0 * al0 + rs0; m0 = mn0;
        l1 = l1 * al1 + rs1; m1 = mn1;

        // rescale O
#pragma unroll
        for (int dt = 0; dt < 8; dt++) {
            o[dt][0] *= al0; o[dt][1] *= al0;
            o[dt][2] *= al1; o[dt][3] *= al1;
        }

        // ---- PV: A-fragments from p via quad shuffles ----
        int srcA = (lane & ~3) | (j >> 1);
        int srcB = srcA | 2;
        bool odd = (j & 1);
#pragma unroll
        for (int ks = 0; ks < 8; ks++) {
            float v0 = __shfl_sync(0xffffffffu, p[ks][0], srcA);
            float v1 = __shfl_sync(0xffffffffu, p[ks][1], srcA);
            float v2 = __shfl_sync(0xffffffffu, p[ks][2], srcA);
            float v3 = __shfl_sync(0xffffffffu, p[ks][3], srcA);
            float w0 = __shfl_sync(0xffffffffu, p[ks][0], srcB);
            float w1 = __shfl_sync(0xffffffffu, p[ks][1], srcB);
            float w2 = __shfl_sync(0xffffffffu, p[ks][2], srcB);
            float w3 = __shfl_sync(0xffffffffu, p[ks][3], srcB);
            uint32_t af[4];
            af[0] = __float_as_uint(odd ? v1 : v0);   // P[q   ][8ks+j  ]
            af[1] = __float_as_uint(odd ? v3 : v2);   // P[q+8 ][8ks+j  ]
            af[2] = __float_as_uint(odd ? w1 : w0);   // P[q   ][8ks+j+4]
            af[3] = __float_as_uint(odd ? w3 : w2);   // P[q+8 ][8ks+j+4]
#pragma unroll
            for (int dt = 0; dt < 8; dt++) {
                uint32_t bf[2];
                int d0 = dt * 8 + q;
                bf[0] = __float_as_uint(Vs[(ks * 8 + j) * 72 + d0]);
                bf[1] = __float_as_uint(Vs[(ks * 8 + 4 + j) * 72 + d0]);
                MMA_TF32(o[dt], af, bf);
            }
        }

        if (kt + 2 < NKT) issue(kt + 2);
    }

    // ---- epilogue: divide by l, write tf32-rounded ----
    float il0 = 1.0f / l0, il1 = 1.0f / l1;
    float* Og = O + (size_t)(b * S + qbase + wid * 16) * D + h * DH;
#pragma unroll
    for (int dt = 0; dt < 8; dt++) {
        int c0 = dt * 8 + 2 * j;
        *(float2*)(Og + (size_t)q * D + c0) =
            make_float2(cvt_tf32f(o[dt][0] * il0), cvt_tf32f(o[dt][1] * il0));
        *(float2*)(Og + (size_t)(q + 8) * D + c0) =
            make_float2(cvt_tf32f(o[dt][2] * il1), cvt_tf32f(o[dt][3] * il1));
    }
}

// ---------------- launch ----------------------------------------------------
extern "C" void kernel_launch(void* const* d_in, const int* in_sizes, int n_in,
                              void* d_out, int out_size) {
    const float* x     = (const float*)d_in[0];
    const float* gamma = (const float*)d_in[1];
    const float* beta  = (const float*)d_in[2];
    const float* wq    = (const float*)d_in[3];
    const float* bq    = (const float*)d_in[4];
    const float* wk    = (const float*)d_in[5];
    const float* bk    = (const float*)d_in[6];
    const float* wv    = (const float*)d_in[7];
    const float* bv    = (const float*)d_in[8];
    const float* wo    = (const float*)d_in[9];
    const float* bo    = (const float*)d_in[10];
    float* out = (float*)d_out;

    float *xn, *q, *k, *v, *att, *rwq, *rwk, *rwv, *rwo;
    cudaGetSymbolAddress((void**)&xn,  g_xn);
    cudaGetSymbolAddress((void**)&q,   g_q);
    cudaGetSymbolAddress((void**)&k,   g_k);
    cudaGetSymbolAddress((void**)&v,   g_v);
    cudaGetSymbolAddress((void**)&att, g_att);
    cudaGetSymbolAddress((void**)&rwq, g_wq);
    cudaGetSymbolAddress((void**)&rwk, g_wk);
    cudaGetSymbolAddress((void**)&rwv, g_wv);
    cudaGetSymbolAddress((void**)&rwo, g_wo);

    int gemm_smem = 3 * GST * (int)sizeof(float);   // 107520 B
    int attn_smem = 3 * AST * (int)sizeof(float);   // 107520 B
    cudaFuncSetAttribute(gemm_tc<true>,
                         cudaFuncAttributeMaxDynamicSharedMemorySize, gemm_smem);
    cudaFuncSetAttribute(gemm_tc<false>,
                         cudaFuncAttributeMaxDynamicSharedMemorySize, gemm_smem);
    cudaFuncSetAttribute(attn_tc,
                         cudaFuncAttributeMaxDynamicSharedMemorySize, attn_smem);

    // 0. round weights to tf32 once per call
    round_w<<<dim3(D * D / 1024, 4), 256>>>(wq, wk, wv, wo, rwq, rwk, rwv, rwo);

    // 1. LayerNorm (tf32-rounded output)
    ln_kernel<<<ROWS, 256>>>(x, gamma, beta, xn);

    // 2. fused Q/K/V projection (rounded outputs)
    dim3 ggrid(D / 128, ROWS / 128, 3);
    gemm_tc<true><<<ggrid, 256, gemm_smem>>>(xn, rwq, rwk, rwv, bq, bk, bv,
                                             q, k, v, D, D);

    // 3. attention (rounded output)
    dim3 agrid(S / 128, B * H);
    attn_tc<<<agrid, 256, attn_smem>>>(q, k, v, att);

    // 4. output projection (fp32 output)
    dim3 ogrid(D / 128, ROWS / 128, 1);
    gemm_tc<false><<<ogrid, 256, gemm_smem>>>(att, rwo, rwo, rwo, bo, bo, bo,
                                              out, out, out, D, D);
}

// round 6
// speedup vs baseline: 4.1544x; 1.0584x over previous
#include <cuda_runtime.h>
#include <math.h>
#include <stdint.h>

// Problem constants
#define B   2
#define S   2048
#define D   1024
#define H   16
#define DH  64
#define ROWS (B*S)           // 4096
#define EPS 1e-5f

// ---------------- scratch (device globals) ---------------------------------
__device__ float g_xn [ROWS * D];
__device__ float g_q  [ROWS * D];
__device__ float g_k  [ROWS * D];
__device__ float g_v  [ROWS * D];   // TRANSPOSED: [B][D][S] = (b*D + c)*S + s
__device__ float g_att[ROWS * D];
__device__ float g_wq [D * D];      // transposed [n][k]
__device__ float g_wk [D * D];
__device__ float g_wv [D * D];
__device__ float g_wo [D * D];

// ---------------- helpers ---------------------------------------------------
__device__ __forceinline__ float cvt_tf32f(float x) {
    uint32_t u;
    asm("cvt.rna.tf32.f32 %0, %1;" : "=r"(u) : "f"(x));
    return __uint_as_float(u);
}

#define MMA_TF32(c, a, b)                                                     \
    asm volatile(                                                             \
        "mma.sync.aligned.m16n8k8.row.col.f32.tf32.tf32.f32 "                 \
        "{%0,%1,%2,%3},{%4,%5,%6,%7},{%8,%9},{%0,%1,%2,%3};"                  \
        : "+f"((c)[0]), "+f"((c)[1]), "+f"((c)[2]), "+f"((c)[3])              \
        : "r"((a)[0]), "r"((a)[1]), "r"((a)[2]), "r"((a)[3]),                 \
          "r"((b)[0]), "r"((b)[1]))

__device__ __forceinline__ uint32_t smaddr(const void* p) {
    return (uint32_t)__cvta_generic_to_shared(p);
}
#define CP_ASYNC16(dst, src)                                                  \
    asm volatile("cp.async.cg.shared.global [%0], [%1], 16;\n"                \
                 :: "r"(dst), "l"(src))
#define CP_COMMIT() asm volatile("cp.async.commit_group;\n")
#define CP_WAIT1()  asm volatile("cp.async.wait_group 1;\n")
#define CP_WAIT0()  asm volatile("cp.async.wait_group 0;\n")

// ---------------- weight transpose + tf32 round -----------------------------
// dst[n][k] = tf32(src[k][n]); blockIdx.z selects matrix.
__global__ void transpose_w(const float* __restrict__ a, const float* __restrict__ b,
                            const float* __restrict__ c, const float* __restrict__ d,
                            float* __restrict__ oa, float* __restrict__ ob,
                            float* __restrict__ oc, float* __restrict__ od) {
    __shared__ float t[32][33];
    const float* src = blockIdx.z == 0 ? a : blockIdx.z == 1 ? b
                     : blockIdx.z == 2 ? c : d;
    float* dst = blockIdx.z == 0 ? oa : blockIdx.z == 1 ? ob
               : blockIdx.z == 2 ? oc : od;
    int bx = blockIdx.x * 32, by = blockIdx.y * 32;
    int tx = threadIdx.x, ty = threadIdx.y;
#pragma unroll
    for (int i = 0; i < 4; i++)
        t[ty + i * 8][tx] = src[(size_t)(by + ty + i * 8) * D + bx + tx];
    __syncthreads();
#pragma unroll
    for (int i = 0; i < 4; i++)
        dst[(size_t)(bx + ty + i * 8) * D + by + tx] =
            cvt_tf32f(t[tx][ty + i * 8]);
}

// ---------------- LayerNorm (writes tf32-rounded output) --------------------
__global__ void ln_kernel(const float* __restrict__ x,
                          const float* __restrict__ gamma,
                          const float* __restrict__ beta,
                          float* __restrict__ out) {
    int row = blockIdx.x;
    const float* xr = x + (size_t)row * D;
    float* orow = out + (size_t)row * D;

    float vals[4];
    float sum = 0.f, sq = 0.f;
#pragma unroll
    for (int i = 0; i < 4; i++) {
        float v = xr[threadIdx.x + i * 256];
        vals[i] = v;
        sum += v; sq += v * v;
    }
#pragma unroll
    for (int o = 16; o >= 1; o >>= 1) {
        sum += __shfl_xor_sync(0xffffffffu, sum, o);
        sq  += __shfl_xor_sync(0xffffffffu, sq , o);
    }
    __shared__ float ssum[8], ssq[8];
    int warp = threadIdx.x >> 5, lane = threadIdx.x & 31;
    if (lane == 0) { ssum[warp] = sum; ssq[warp] = sq; }
    __syncthreads();
    float ts = 0.f, tq = 0.f;
#pragma unroll
    for (int w = 0; w < 8; w++) { ts += ssum[w]; tq += ssq[w]; }
    float mu  = ts * (1.0f / D);
    float var = tq * (1.0f / D) - mu * mu;
    float rstd = rsqrtf(var + EPS);
#pragma unroll
    for (int i = 0; i < 4; i++) {
        int c = threadIdx.x + i * 256;
        orow[c] = cvt_tf32f((vals[i] - mu) * rstd * gamma[c] + beta[c]);
    }
}

// ---------------- tf32 GEMM, transposed W, vectorized fragments -------------
// Block tile 128x128, BK=32, 256 threads = 8 warps (4 M x 2 N), warp 32x64.
// W is stored TRANSPOSED [n][k]. Logical-k remap: lane slot (j, j+4) reads
// physical (2j, 2j+1) -> all fragment loads are conflict-free LDS.64.
// z==2 writes C transposed per (b): C[(b*D + col)*S + s] (for V).
// 3-STAGE cp.async ring (depth-2 prefetch REQUIRES 3 buffers: stage kt+2
// written while other warps may still read stage kt under only 2 buffers).
#define GST 10240   // floats per stage: 128*40 (A) + 128*40 (B)

template <bool RND>
__global__ void __launch_bounds__(256)
gemm_tc(const float* __restrict__ A,
        const float* __restrict__ W0, const float* __restrict__ W1,
        const float* __restrict__ W2,
        const float* __restrict__ b0, const float* __restrict__ b1,
        const float* __restrict__ b2,
        float* __restrict__ C0, float* __restrict__ C1, float* __restrict__ C2,
        int K, int N) {
    extern __shared__ float sm[];

    int z = blockIdx.z;
    const float* W = z == 0 ? W0 : z == 1 ? W1 : W2;
    const float* bias = z == 0 ? b0 : z == 1 ? b1 : b2;
    float* C = z == 0 ? C0 : z == 1 ? C1 : C2;

    int tid = threadIdx.x, lane = tid & 31, wid = tid >> 5;
    int q = lane >> 2, j = lane & 3;
    int wm = wid & 3, wn = wid >> 2;
    int mBase = blockIdx.y * 128, nBase = blockIdx.x * 128;

    float acc[2][8][4] = {};

    // per-thread load coords (both tiles are 128 rows x 32 cols)
    int rl = tid >> 3, cl4 = (tid & 7) << 2;

    auto issue = [&](int kt) {
        float* As = sm + (kt % 3) * GST;
        float* Bs = As + 5120;
        int k0 = kt * 32;
#pragma unroll
        for (int i = 0; i < 4; i++)
            CP_ASYNC16(smaddr(As + (rl + i * 32) * 40 + cl4),
                       A + (size_t)(mBase + rl + i * 32) * K + k0 + cl4);
#pragma unroll
        for (int i = 0; i < 4; i++)
            CP_ASYNC16(smaddr(Bs + (rl + i * 32) * 40 + cl4),
                       W + (size_t)(nBase + rl + i * 32) * K + k0 + cl4);
        CP_COMMIT();
    };

    int NT = K / 32;
    issue(0);
    if (NT > 1) issue(1);

    for (int kt = 0; kt < NT; kt++) {
        if (kt + 1 < NT) { CP_WAIT1(); } else { CP_WAIT0(); }
        __syncthreads();

        float* As = sm + (kt % 3) * GST;
        float* Bs = As + 5120;
#pragma unroll
        for (int ks = 0; ks < 4; ks++) {
            int kc = ks * 8 + 2 * j;
            uint32_t a[2][4], b[8][2];
#pragma unroll
            for (int mt = 0; mt < 2; mt++) {
                int r = wm * 32 + mt * 16 + q;
                float2 lo = *(float2*)&As[r * 40 + kc];
                float2 hi = *(float2*)&As[(r + 8) * 40 + kc];
                a[mt][0] = __float_as_uint(lo.x);
                a[mt][1] = __float_as_uint(hi.x);
                a[mt][2] = __float_as_uint(lo.y);
                a[mt][3] = __float_as_uint(hi.y);
            }
#pragma unroll
            for (int nt = 0; nt < 8; nt++) {
                int c = wn * 64 + nt * 8 + q;
                float2 w2 = *(float2*)&Bs[c * 40 + kc];
                b[nt][0] = __float_as_uint(w2.x);
                b[nt][1] = __float_as_uint(w2.y);
            }
#pragma unroll
            for (int mt = 0; mt < 2; mt++)
#pragma unroll
                for (int nt = 0; nt < 8; nt++)
                    MMA_TF32(acc[mt][nt], a[mt], b[nt]);
        }

        if (kt + 2 < NT) issue(kt + 2);
    }

    // epilogue
    bool transposed = (z == 2);
#pragma unroll
    for (int mt = 0; mt < 2; mt++) {
        int r0 = mBase + wm * 32 + mt * 16 + q;
#pragma unroll
        for (int nt = 0; nt < 8; nt++) {
            int c0 = nBase + wn * 64 + nt * 8 + 2 * j;
            float2 b2 = *(const float2*)(bias + c0);
            float v00 = acc[mt][nt][0] + b2.x, v01 = acc[mt][nt][1] + b2.y;
            float v10 = acc[mt][nt][2] + b2.x, v11 = acc[mt][nt][3] + b2.y;
            if (RND) {
                v00 = cvt_tf32f(v00); v01 = cvt_tf32f(v01);
                v10 = cvt_tf32f(v10); v11 = cvt_tf32f(v11);
            }
            if (!transposed) {
                *(float2*)(C + (size_t)r0 * N + c0) = make_float2(v00, v01);
                *(float2*)(C + (size_t)(r0 + 8) * N + c0) = make_float2(v10, v11);
            } else {
                int bb = r0 >> 11, ss = r0 & (S - 1);
                size_t base = ((size_t)(bb * D + c0)) * S + ss;
                C[base]         = v00;   // (c0  , ss  )
                C[base + S]     = v01;   // (c0+1, ss  )
                C[base + 8]     = v10;   // (c0  , ss+8)
                C[base + S + 8] = v11;   // (c0+1, ss+8)
            }
        }
    }
}

// ---------------- flash attention: vectorized fragments, zero shuffles ------
// grid (S/128, B*H); 256 thr = 8 warps; warp w owns q-rows w*16..+15 and the
// full 64-key tile. Logical-k remap makes every smem fragment a conflict-free
// LDS.64 AND makes the PV A-fragment the thread's own QK^T C-fragment.
// V is transposed [d][s] in gmem. 3-stage cp.async ring, 1 sync per tile.
#define AST 9216   // floats per stage: 64*72 (K) + 64*72 (V^T)

__global__ void __launch_bounds__(256, 2)
attn_tc(const float* __restrict__ Q, const float* __restrict__ K,
        const float* __restrict__ V, float* __restrict__ O) {
    extern __shared__ float sm[];

    int tid = threadIdx.x, lane = tid & 31, wid = tid >> 5;
    int q = lane >> 2, j = lane & 3;
    int bh = blockIdx.y, b = bh >> 4, h = bh & 15;
    int qbase = blockIdx.x * 128;

    const float* Kg = K + (size_t)(b * S) * D + h * DH;
    const float* VT = V + ((size_t)b * D + h * DH) * S;   // [d][s]
    const float* Qg = Q + (size_t)(b * S + qbase + wid * 16) * D + h * DH;

    int rkv = tid >> 4, ckv = (tid & 15) << 2;

    auto issue = [&](int kt) {
        float* Ks = sm + (kt % 3) * AST;
        float* Vs = Ks + 4608;
        const float* Kt = Kg + (size_t)kt * 64 * D;
        const float* Vt = VT + (size_t)kt * 64;
#pragma unroll
        for (int i = 0; i < 4; i++) {
            int r = rkv + i * 16;
            CP_ASYNC16(smaddr(Ks + r * 72 + ckv), Kt + (size_t)r * D + ckv);
            CP_ASYNC16(smaddr(Vs + r * 72 + ckv), Vt + (size_t)r * S + ckv);
        }
        CP_COMMIT();
    };

    // Q fragments (logical-k remap: slots (j, j+4) = physical (2j, 2j+1)),
    // scaled by 1/8 (exact)
    uint32_t qf[8][4];
#pragma unroll
    for (int ks = 0; ks < 8; ks++) {
        int d0 = ks * 8 + 2 * j;
        float2 lo = *(const float2*)(Qg + (size_t)q * D + d0);
        float2 hi = *(const float2*)(Qg + (size_t)(q + 8) * D + d0);
        qf[ks][0] = __float_as_uint(lo.x * 0.125f);
        qf[ks][1] = __float_as_uint(hi.x * 0.125f);
        qf[ks][2] = __float_as_uint(lo.y * 0.125f);
        qf[ks][3] = __float_as_uint(hi.y * 0.125f);
    }

    float o[8][4] = {};
    float m0 = -1e30f, m1 = -1e30f, l0 = 0.f, l1 = 0.f;

    issue(0);
    issue(1);

    const int NKT = S / 64;
    for (int kt = 0; kt < NKT; kt++) {
        if (kt + 1 < NKT) { CP_WAIT1(); } else { CP_WAIT0(); }
        __syncthreads();

        const float* Ks = sm + (kt % 3) * AST;
        const float* Vs = Ks + 4608;

        // ---- QK^T into register fragments p[8][4] ----
        float p[8][4];
#pragma unroll
        for (int pr = 0; pr < 4; pr++) {
            float s0[4] = {}, s1[4] = {};
            int key0 = pr * 16 + q;
#pragma unroll
            for (int ks = 0; ks < 8; ks++) {
                int kc = ks * 8 + 2 * j;
                float2 k0 = *(const float2*)&Ks[key0 * 72 + kc];
                float2 k1 = *(const float2*)&Ks[(key0 + 8) * 72 + kc];
                uint32_t bf0[2] = { __float_as_uint(k0.x), __float_as_uint(k0.y) };
                uint32_t bf1[2] = { __float_as_uint(k1.x), __float_as_uint(k1.y) };
                MMA_TF32(s0, qf[ks], bf0);
                MMA_TF32(s1, qf[ks], bf1);
            }
#pragma unroll
            for (int u = 0; u < 4; u++) {
                p[2 * pr][u] = s0[u];
                p[2 * pr + 1][u] = s1[u];
            }
        }

        // ---- register online softmax (rows q and q+8) ----
        float mx0 = p[0][0], mx1 = p[0][2];
#pragma unroll
        for (int nt = 0; nt < 8; nt++) {
            mx0 = fmaxf(mx0, fmaxf(p[nt][0], p[nt][1]));
            mx1 = fmaxf(mx1, fmaxf(p[nt][2], p[nt][3]));
        }
        mx0 = fmaxf(mx0, __shfl_xor_sync(0xffffffffu, mx0, 1));
        mx0 = fmaxf(mx0, __shfl_xor_sync(0xffffffffu, mx0, 2));
        mx1 = fmaxf(mx1, __shfl_xor_sync(0xffffffffu, mx1, 1));
        mx1 = fmaxf(mx1, __shfl_xor_sync(0xffffffffu, mx1, 2));

        float mn0 = fmaxf(m0, mx0), mn1 = fmaxf(m1, mx1);
        float al0 = __expf(m0 - mn0), al1 = __expf(m1 - mn1);
        float rs0 = 0.f, rs1 = 0.f;
#pragma unroll
        for (int nt = 0; nt < 8; nt++) {
            float e0 = __expf(p[nt][0] - mn0);
            float e1 = __expf(p[nt][1] - mn0);
            float e2 = __expf(p[nt][2] - mn1);
            float e3 = __expf(p[nt][3] - mn1);
            rs0 += e0 + e1; rs1 += e2 + e3;
            p[nt][0] = cvt_tf32f(e0); p[nt][1] = cvt_tf32f(e1);
            p[nt][2] = cvt_tf32f(e2); p[nt][3] = cvt_tf32f(e3);
        }
        rs0 += __shfl_xor_sync(0xffffffffu, rs0, 1);
        rs0 += __shfl_xor_sync(0xffffffffu, rs0, 2);
        rs1 += __shfl_xor_sync(0xffffffffu, rs1, 1);
        rs1 += __shfl_xor_sync(0xffffffffu, rs1, 2);
        l0 = l0 * al0 + rs0; m0 = mn0;
        l1 = l1 * al1 + rs1; m1 = mn1;

        // rescale O
#pragma unroll
        for (int dt = 0; dt < 8; dt++) {
            o[dt][0] *= al0; o[dt][1] *= al0;
            o[dt][2] *= al1; o[dt][3] *= al1;
        }

        // ---- PV: A-fragment IS the thread's own p[nt]; B = V^T float2 ----
#pragma unroll
        for (int nt = 0; nt < 8; nt++) {
            uint32_t af[4];
            af[0] = __float_as_uint(p[nt][0]);   // P[q  ][nt*8+2j]
            af[1] = __float_as_uint(p[nt][2]);   // P[q+8][nt*8+2j]
            af[2] = __float_as_uint(p[nt][1]);   // P[q  ][nt*8+2j+1]
            af[3] = __float_as_uint(p[nt][3]);   // P[q+8][nt*8+2j+1]
            int kc = nt * 8 + 2 * j;
#pragma unroll
            for (int dt = 0; dt < 8; dt++) {
                float2 v2 = *(const float2*)&Vs[(dt * 8 + q) * 72 + kc];
                uint32_t bf[2] = { __float_as_uint(v2.x), __float_as_uint(v2.y) };
                MMA_TF32(o[dt], af, bf);
            }
        }

        if (kt + 2 < NKT) issue(kt + 2);
    }

    // ---- epilogue: divide by l, write tf32-rounded ----
    float il0 = 1.0f / l0, il1 = 1.0f / l1;
    float* Og = O + (size_t)(b * S + qbase + wid * 16) * D + h * DH;
#pragma unroll
    for (int dt = 0; dt < 8; dt++) {
        int c0 = dt * 8 + 2 * j;
        *(float2*)(Og + (size_t)q * D + c0) =
            make_float2(cvt_tf32f(o[dt][0] * il0), cvt_tf32f(o[dt][1] * il0));
        *(float2*)(Og + (size_t)(q + 8) * D + c0) =
            make_float2(cvt_tf32f(o[dt][2] * il1), cvt_tf32f(o[dt][3] * il1));
    }
}

// ---------------- launch ----------------------------------------------------
extern "C" void kernel_launch(void* const* d_in, const int* in_sizes, int n_in,
                              void* d_out, int out_size) {
    const float* x     = (const float*)d_in[0];
    const float* gamma = (const float*)d_in[1];
    const float* beta  = (const float*)d_in[2];
    const float* wq    = (const float*)d_in[3];
    const float* bq    = (const float*)d_in[4];
    const float* wk    = (const float*)d_in[5];
    const float* bk    = (const float*)d_in[6];
    const float* wv    = (const float*)d_in[7];
    const float* bv    = (const float*)d_in[8];
    const float* wo    = (const float*)d_in[9];
    const float* bo    = (const float*)d_in[10];
    float* out = (float*)d_out;

    float *xn, *q, *k, *v, *att, *rwq, *rwk, *rwv, *rwo;
    cudaGetSymbolAddress((void**)&xn,  g_xn);
    cudaGetSymbolAddress((void**)&q,   g_q);
    cudaGetSymbolAddress((void**)&k,   g_k);
    cudaGetSymbolAddress((void**)&v,   g_v);
    cudaGetSymbolAddress((void**)&att, g_att);
    cudaGetSymbolAddress((void**)&rwq, g_wq);
    cudaGetSymbolAddress((void**)&rwk, g_wk);
    cudaGetSymbolAddress((void**)&rwv, g_wv);
    cudaGetSymbolAddress((void**)&rwo, g_wo);

    int gemm_smem = 3 * GST * (int)sizeof(float);   // 122880 B
    int attn_smem = 3 * AST * (int)sizeof(float);   // 110592 B
    cudaFuncSetAttribute(gemm_tc<true>,
                         cudaFuncAttributeMaxDynamicSharedMemorySize, gemm_smem);
    cudaFuncSetAttribute(gemm_tc<false>,
                         cudaFuncAttributeMaxDynamicSharedMemorySize, gemm_smem);
    cudaFuncSetAttribute(attn_tc,
                         cudaFuncAttributeMaxDynamicSharedMemorySize, attn_smem);

    // 0. transpose + tf32-round weights
    transpose_w<<<dim3(D / 32, D / 32, 4), dim3(32, 8)>>>(
        wq, wk, wv, wo, rwq, rwk, rwv, rwo);

    // 1. LayerNorm (tf32-rounded output)
    ln_kernel<<<ROWS, 256>>>(x, gamma, beta, xn);

    // 2. fused Q/K/V projection (rounded outputs; V written transposed)
    dim3 ggrid(D / 128, ROWS / 128, 3);
    gemm_tc<true><<<ggrid, 256, gemm_smem>>>(xn, rwq, rwk, rwv, bq, bk, bv,
                                             q, k, v, D, D);

    // 3. attention (rounded output)
    dim3 agrid(S / 128, B * H);
    attn_tc<<<agrid, 256, attn_smem>>>(q, k, v, att);

    // 4. output projection (fp32 output)
    dim3 ogrid(D / 128, ROWS / 128, 1);
    gemm_tc<false><<<ogrid, 256, gemm_smem>>>(att, rwo, rwo, rwo, bo, bo, bo,
                                              out, out, out, D, D);
}

// round 7
// speedup vs baseline: 4.4141x; 1.0625x over previous
#include <cuda_runtime.h>
#include <math.h>
#include <stdint.h>

// Problem constants
#define B   2
#define S   2048
#define D   1024
#define H   16
#define DH  64
#define ROWS (B*S)           // 4096
#define EPS 1e-5f

// ---------------- scratch (device globals) ---------------------------------
__device__ float g_xn [ROWS * D];
__device__ float g_q  [ROWS * D];
__device__ float g_k  [ROWS * D];
__device__ float g_v  [ROWS * D];   // TRANSPOSED: [B][D][S] = (b*D + c)*S + s
__device__ float g_att[ROWS * D];
__device__ float g_wq [D * D];      // transposed [n][k]
__device__ float g_wk [D * D];
__device__ float g_wv [D * D];
__device__ float g_wo [D * D];

// ---------------- helpers ---------------------------------------------------
__device__ __forceinline__ float cvt_tf32f(float x) {
    uint32_t u;
    asm("cvt.rna.tf32.f32 %0, %1;" : "=r"(u) : "f"(x));
    return __uint_as_float(u);
}

#define MMA_TF32(c, a, b)                                                     \
    asm volatile(                                                             \
        "mma.sync.aligned.m16n8k8.row.col.f32.tf32.tf32.f32 "                 \
        "{%0,%1,%2,%3},{%4,%5,%6,%7},{%8,%9},{%0,%1,%2,%3};"                  \
        : "+f"((c)[0]), "+f"((c)[1]), "+f"((c)[2]), "+f"((c)[3])              \
        : "r"((a)[0]), "r"((a)[1]), "r"((a)[2]), "r"((a)[3]),                 \
          "r"((b)[0]), "r"((b)[1]))

__device__ __forceinline__ uint32_t smaddr(const void* p) {
    return (uint32_t)__cvta_generic_to_shared(p);
}
#define CP_ASYNC16(dst, src)                                                  \
    asm volatile("cp.async.cg.shared.global [%0], [%1], 16;\n"                \
                 :: "r"(dst), "l"(src))
#define CP_COMMIT() asm volatile("cp.async.commit_group;\n")
#define CP_WAIT1()  asm volatile("cp.async.wait_group 1;\n")
#define CP_WAIT0()  asm volatile("cp.async.wait_group 0;\n")

// ---------------- weight transpose + tf32 round -----------------------------
__global__ void transpose_w(const float* __restrict__ a, const float* __restrict__ b,
                            const float* __restrict__ c, const float* __restrict__ d,
                            float* __restrict__ oa, float* __restrict__ ob,
                            float* __restrict__ oc, float* __restrict__ od) {
    __shared__ float t[32][33];
    const float* src = blockIdx.z == 0 ? a : blockIdx.z == 1 ? b
                     : blockIdx.z == 2 ? c : d;
    float* dst = blockIdx.z == 0 ? oa : blockIdx.z == 1 ? ob
               : blockIdx.z == 2 ? oc : od;
    int bx = blockIdx.x * 32, by = blockIdx.y * 32;
    int tx = threadIdx.x, ty = threadIdx.y;
#pragma unroll
    for (int i = 0; i < 4; i++)
        t[ty + i * 8][tx] = src[(size_t)(by + ty + i * 8) * D + bx + tx];
    __syncthreads();
#pragma unroll
    for (int i = 0; i < 4; i++)
        dst[(size_t)(bx + ty + i * 8) * D + by + tx] =
            cvt_tf32f(t[tx][ty + i * 8]);
}

// ---------------- LayerNorm (writes tf32-rounded output) --------------------
__global__ void ln_kernel(const float* __restrict__ x,
                          const float* __restrict__ gamma,
                          const float* __restrict__ beta,
                          float* __restrict__ out) {
    int row = blockIdx.x;
    const float* xr = x + (size_t)row * D;
    float* orow = out + (size_t)row * D;

    float vals[4];
    float sum = 0.f, sq = 0.f;
#pragma unroll
    for (int i = 0; i < 4; i++) {
        float v = xr[threadIdx.x + i * 256];
        vals[i] = v;
        sum += v; sq += v * v;
    }
#pragma unroll
    for (int o = 16; o >= 1; o >>= 1) {
        sum += __shfl_xor_sync(0xffffffffu, sum, o);
        sq  += __shfl_xor_sync(0xffffffffu, sq , o);
    }
    __shared__ float ssum[8], ssq[8];
    int warp = threadIdx.x >> 5, lane = threadIdx.x & 31;
    if (lane == 0) { ssum[warp] = sum; ssq[warp] = sq; }
    __syncthreads();
    float ts = 0.f, tq = 0.f;
#pragma unroll
    for (int w = 0; w < 8; w++) { ts += ssum[w]; tq += ssq[w]; }
    float mu  = ts * (1.0f / D);
    float var = tq * (1.0f / D) - mu * mu;
    float rstd = rsqrtf(var + EPS);
#pragma unroll
    for (int i = 0; i < 4; i++) {
        int c = threadIdx.x + i * 256;
        orow[c] = cvt_tf32f((vals[i] - mu) * rstd * gamma[c] + beta[c]);
    }
}

// ---------------- tf32 GEMM, 2-stage cp.async, 2 CTAs/SM --------------------
// Block tile 128x128, BK=32, 256 threads = 8 warps (4 M x 2 N), warp 32x64.
// W stored TRANSPOSED [n][k]; logical-k remap -> conflict-free LDS.64 frags.
// Pipeline: wait(kt) -> sync -> issue(kt+1) -> compute(kt). Buffer (kt+1)&1
// was last read by compute(kt-1), which the sync fences -> race-free with
// only 2 buffers and ONE sync per slab.
// z==2: output tile staged through smem transpose, coalesced V^T stores.
#define GST 10240   // floats per stage: 128*40 (A) + 128*40 (B)

template <bool RND>
__global__ void __launch_bounds__(256, 2)
gemm_tc(const float* __restrict__ A,
        const float* __restrict__ W0, const float* __restrict__ W1,
        const float* __restrict__ W2,
        const float* __restrict__ b0, const float* __restrict__ b1,
        const float* __restrict__ b2,
        float* __restrict__ C0, float* __restrict__ C1, float* __restrict__ C2,
        int K, int N) {
    extern __shared__ float sm[];

    int z = blockIdx.z;
    const float* W = z == 0 ? W0 : z == 1 ? W1 : W2;
    const float* bias = z == 0 ? b0 : z == 1 ? b1 : b2;
    float* C = z == 0 ? C0 : z == 1 ? C1 : C2;

    int tid = threadIdx.x, lane = tid & 31, wid = tid >> 5;
    int q = lane >> 2, j = lane & 3;
    int wm = wid & 3, wn = wid >> 2;
    int mBase = blockIdx.y * 128, nBase = blockIdx.x * 128;

    float acc[2][8][4] = {};

    int rl = tid >> 3, cl4 = (tid & 7) << 2;

    auto issue = [&](int kt) {
        float* As = sm + (kt & 1) * GST;
        float* Bs = As + 5120;
        int k0 = kt * 32;
#pragma unroll
        for (int i = 0; i < 4; i++)
            CP_ASYNC16(smaddr(As + (rl + i * 32) * 40 + cl4),
                       A + (size_t)(mBase + rl + i * 32) * K + k0 + cl4);
#pragma unroll
        for (int i = 0; i < 4; i++)
            CP_ASYNC16(smaddr(Bs + (rl + i * 32) * 40 + cl4),
                       W + (size_t)(nBase + rl + i * 32) * K + k0 + cl4);
        CP_COMMIT();
    };

    int NT = K / 32;
    issue(0);

    for (int kt = 0; kt < NT; kt++) {
        CP_WAIT0();
        __syncthreads();
        if (kt + 1 < NT) issue(kt + 1);

        float* As = sm + (kt & 1) * GST;
        float* Bs = As + 5120;
#pragma unroll
        for (int ks = 0; ks < 4; ks++) {
            int kc = ks * 8 + 2 * j;
            uint32_t a[2][4], b[8][2];
#pragma unroll
            for (int mt = 0; mt < 2; mt++) {
                int r = wm * 32 + mt * 16 + q;
                float2 lo = *(float2*)&As[r * 40 + kc];
                float2 hi = *(float2*)&As[(r + 8) * 40 + kc];
                a[mt][0] = __float_as_uint(lo.x);
                a[mt][1] = __float_as_uint(hi.x);
                a[mt][2] = __float_as_uint(lo.y);
                a[mt][3] = __float_as_uint(hi.y);
            }
#pragma unroll
            for (int nt = 0; nt < 8; nt++) {
                int c = wn * 64 + nt * 8 + q;
                float2 w2 = *(float2*)&Bs[c * 40 + kc];
                b[nt][0] = __float_as_uint(w2.x);
                b[nt][1] = __float_as_uint(w2.y);
            }
#pragma unroll
            for (int mt = 0; mt < 2; mt++)
#pragma unroll
                for (int nt = 0; nt < 8; nt++)
                    MMA_TF32(acc[mt][nt], a[mt], b[nt]);
        }
    }

    bool transposed = (z == 2);
    if (transposed) __syncthreads();   // smem reuse: all warps done with tiles

#pragma unroll
    for (int mt = 0; mt < 2; mt++) {
        int rl0 = wm * 32 + mt * 16 + q;
        int r0 = mBase + rl0;
#pragma unroll
        for (int nt = 0; nt < 8; nt++) {
            int cl0 = wn * 64 + nt * 8 + 2 * j;
            int c0 = nBase + cl0;
            float2 b2 = *(const float2*)(bias + c0);
            float v00 = acc[mt][nt][0] + b2.x, v01 = acc[mt][nt][1] + b2.y;
            float v10 = acc[mt][nt][2] + b2.x, v11 = acc[mt][nt][3] + b2.y;
            if (RND) {
                v00 = cvt_tf32f(v00); v01 = cvt_tf32f(v01);
                v10 = cvt_tf32f(v10); v11 = cvt_tf32f(v11);
            }
            if (!transposed) {
                *(float2*)(C + (size_t)r0 * N + c0) = make_float2(v00, v01);
                *(float2*)(C + (size_t)(r0 + 8) * N + c0) = make_float2(v10, v11);
            } else {
                // stage into smem transposed: T[c][s], pad 132
                sm[(size_t)cl0 * 132 + rl0]           = v00;
                sm[(size_t)(cl0 + 1) * 132 + rl0]     = v01;
                sm[(size_t)cl0 * 132 + rl0 + 8]       = v10;
                sm[(size_t)(cl0 + 1) * 132 + rl0 + 8] = v11;
            }
        }
    }

    if (transposed) {
        __syncthreads();
        int bb = mBase >> 11, s0 = mBase & (S - 1);
        // coalesced store: 4 passes x (8 warps x 4 rows); 8 lanes cover 128B
        int rowd = wid * 4 + (lane >> 3);
        int colb = (lane & 7) * 4;
#pragma unroll
        for (int ps = 0; ps < 4; ps++) {
            int c = ps * 32 + rowd;
            float* dst = C + ((size_t)(bb * D + nBase + c)) * S + s0;
            const float* srcr = sm + (size_t)c * 132;
#pragma unroll
            for (int i = 0; i < 4; i++) {
                int col = colb + i * 32;
                *(float4*)(dst + col) = *(const float4*)(srcr + col);
            }
        }
    }
}

// ---------------- flash attention: 8-chain QK^T, vectorized frags -----------
// grid (S/128, B*H); 256 thr = 8 warps; warp w owns q-rows w*16..+15 and the
// full 64-key tile. PV A-fragment is the thread's own QK^T C-fragment.
// V transposed [d][s] in gmem. 3-stage cp.async ring, 1 sync per tile.
#define AST 9216   // floats per stage: 64*72 (K) + 64*72 (V^T)

__global__ void __launch_bounds__(256, 2)
attn_tc(const float* __restrict__ Q, const float* __restrict__ K,
        const float* __restrict__ V, float* __restrict__ O) {
    extern __shared__ float sm[];

    int tid = threadIdx.x, lane = tid & 31, wid = tid >> 5;
    int q = lane >> 2, j = lane & 3;
    int bh = blockIdx.y, b = bh >> 4, h = bh & 15;
    int qbase = blockIdx.x * 128;

    const float* Kg = K + (size_t)(b * S) * D + h * DH;
    const float* VT = V + ((size_t)b * D + h * DH) * S;   // [d][s]
    const float* Qg = Q + (size_t)(b * S + qbase + wid * 16) * D + h * DH;

    int rkv = tid >> 4, ckv = (tid & 15) << 2;

    auto issue = [&](int kt) {
        float* Ks = sm + (kt % 3) * AST;
        float* Vs = Ks + 4608;
        const float* Kt = Kg + (size_t)kt * 64 * D;
        const float* Vt = VT + (size_t)kt * 64;
#pragma unroll
        for (int i = 0; i < 4; i++) {
            int r = rkv + i * 16;
            CP_ASYNC16(smaddr(Ks + r * 72 + ckv), Kt + (size_t)r * D + ckv);
            CP_ASYNC16(smaddr(Vs + r * 72 + ckv), Vt + (size_t)r * S + ckv);
        }
        CP_COMMIT();
    };

    // Q fragments (logical-k remap), scaled by 1/8 (exact)
    uint32_t qf[8][4];
#pragma unroll
    for (int ks = 0; ks < 8; ks++) {
        int d0 = ks * 8 + 2 * j;
        float2 lo = *(const float2*)(Qg + (size_t)q * D + d0);
        float2 hi = *(const float2*)(Qg + (size_t)(q + 8) * D + d0);
        qf[ks][0] = __float_as_uint(lo.x * 0.125f);
        qf[ks][1] = __float_as_uint(hi.x * 0.125f);
        qf[ks][2] = __float_as_uint(lo.y * 0.125f);
        qf[ks][3] = __float_as_uint(hi.y * 0.125f);
    }

    float o[8][4] = {};
    float m0 = -1e30f, m1 = -1e30f, l0 = 0.f, l1 = 0.f;

    issue(0);
    issue(1);

    const int NKT = S / 64;
    for (int kt = 0; kt < NKT; kt++) {
        if (kt + 1 < NKT) { CP_WAIT1(); } else { CP_WAIT0(); }
        __syncthreads();

        const float* Ks = sm + (kt % 3) * AST;
        const float* Vs = Ks + 4608;

        // ---- QK^T: ks-outer -> 8 independent MMA chains in flight ----
        float p[8][4] = {};
#pragma unroll
        for (int ks = 0; ks < 8; ks++) {
            int kc = ks * 8 + 2 * j;
#pragma unroll
            for (int pr = 0; pr < 4; pr++) {
                int key0 = pr * 16 + q;
                float2 k0 = *(const float2*)&Ks[key0 * 72 + kc];
                float2 k1 = *(const float2*)&Ks[(key0 + 8) * 72 + kc];
                uint32_t bf0[2] = { __float_as_uint(k0.x), __float_as_uint(k0.y) };
                uint32_t bf1[2] = { __float_as_uint(k1.x), __float_as_uint(k1.y) };
                MMA_TF32(p[2 * pr], qf[ks], bf0);
                MMA_TF32(p[2 * pr + 1], qf[ks], bf1);
            }
        }

        // ---- register online softmax (rows q and q+8) ----
        float mx0 = p[0][0], mx1 = p[0][2];
#pragma unroll
        for (int nt = 0; nt < 8; nt++) {
            mx0 = fmaxf(mx0, fmaxf(p[nt][0], p[nt][1]));
            mx1 = fmaxf(mx1, fmaxf(p[nt][2], p[nt][3]));
        }
        mx0 = fmaxf(mx0, __shfl_xor_sync(0xffffffffu, mx0, 1));
        mx0 = fmaxf(mx0, __shfl_xor_sync(0xffffffffu, mx0, 2));
        mx1 = fmaxf(mx1, __shfl_xor_sync(0xffffffffu, mx1, 1));
        mx1 = fmaxf(mx1, __shfl_xor_sync(0xffffffffu, mx1, 2));

        float mn0 = fmaxf(m0, mx0), mn1 = fmaxf(m1, mx1);
        float al0 = __expf(m0 - mn0), al1 = __expf(m1 - mn1);
        float rs0 = 0.f, rs1 = 0.f;
#pragma unroll
        for (int nt = 0; nt < 8; nt++) {
            float e0 = __expf(p[nt][0] - mn0);
            float e1 = __expf(p[nt][1] - mn0);
            float e2 = __expf(p[nt][2] - mn1);
            float e3 = __expf(p[nt][3] - mn1);
            rs0 += e0 + e1; rs1 += e2 + e3;
            p[nt][0] = cvt_tf32f(e0); p[nt][1] = cvt_tf32f(e1);
            p[nt][2] = cvt_tf32f(e2); p[nt][3] = cvt_tf32f(e3);
        }
        rs0 += __shfl_xor_sync(0xffffffffu, rs0, 1);
        rs0 += __shfl_xor_sync(0xffffffffu, rs0, 2);
        rs1 += __shfl_xor_sync(0xffffffffu, rs1, 1);
        rs1 += __shfl_xor_sync(0xffffffffu, rs1, 2);
        l0 = l0 * al0 + rs0; m0 = mn0;
        l1 = l1 * al1 + rs1; m1 = mn1;

        // rescale O
#pragma unroll
        for (int dt = 0; dt < 8; dt++) {
            o[dt][0] *= al0; o[dt][1] *= al0;
            o[dt][2] *= al1; o[dt][3] *= al1;
        }

        // ---- PV: A-fragment IS the thread's own p[nt]; B = V^T float2 ----
#pragma unroll
        for (int nt = 0; nt < 8; nt++) {
            uint32_t af[4];
            af[0] = __float_as_uint(p[nt][0]);   // P[q  ][nt*8+2j]
            af[1] = __float_as_uint(p[nt][2]);   // P[q+8][nt*8+2j]
            af[2] = __float_as_uint(p[nt][1]);   // P[q  ][nt*8+2j+1]
            af[3] = __float_as_uint(p[nt][3]);   // P[q+8][nt*8+2j+1]
            int kc = nt * 8 + 2 * j;
#pragma unroll
            for (int dt = 0; dt < 8; dt++) {
                float2 v2 = *(const float2*)&Vs[(dt * 8 + q) * 72 + kc];
                uint32_t bf[2] = { __float_as_uint(v2.x), __float_as_uint(v2.y) };
                MMA_TF32(o[dt], af, bf);
            }
        }

        if (kt + 2 < NKT) issue(kt + 2);
    }

    // ---- epilogue: divide by l, write tf32-rounded ----
    float il0 = 1.0f / l0, il1 = 1.0f / l1;
    float* Og = O + (size_t)(b * S + qbase + wid * 16) * D + h * DH;
#pragma unroll
    for (int dt = 0; dt < 8; dt++) {
        int c0 = dt * 8 + 2 * j;
        *(float2*)(Og + (size_t)q * D + c0) =
            make_float2(cvt_tf32f(o[dt][0] * il0), cvt_tf32f(o[dt][1] * il0));
        *(float2*)(Og + (size_t)(q + 8) * D + c0) =
            make_float2(cvt_tf32f(o[dt][2] * il1), cvt_tf32f(o[dt][3] * il1));
    }
}

// ---------------- launch ----------------------------------------------------
extern "C" void kernel_launch(void* const* d_in, const int* in_sizes, int n_in,
                              void* d_out, int out_size) {
    const float* x     = (const float*)d_in[0];
    const float* gamma = (const float*)d_in[1];
    const float* beta  = (const float*)d_in[2];
    const float* wq    = (const float*)d_in[3];
    const float* bq    = (const float*)d_in[4];
    const float* wk    = (const float*)d_in[5];
    const float* bk    = (const float*)d_in[6];
    const float* wv    = (const float*)d_in[7];
    const float* bv    = (const float*)d_in[8];
    const float* wo    = (const float*)d_in[9];
    const float* bo    = (const float*)d_in[10];
    float* out = (float*)d_out;

    float *xn, *q, *k, *v, *att, *rwq, *rwk, *rwv, *rwo;
    cudaGetSymbolAddress((void**)&xn,  g_xn);
    cudaGetSymbolAddress((void**)&q,   g_q);
    cudaGetSymbolAddress((void**)&k,   g_k);
    cudaGetSymbolAddress((void**)&v,   g_v);
    cudaGetSymbolAddress((void**)&att, g_att);
    cudaGetSymbolAddress((void**)&rwq, g_wq);
    cudaGetSymbolAddress((void**)&rwk, g_wk);
    cudaGetSymbolAddress((void**)&rwv, g_wv);
    cudaGetSymbolAddress((void**)&rwo, g_wo);

    int gemm_smem = 2 * GST * (int)sizeof(float);   // 81920 B (2 CTAs/SM)
    int attn_smem = 3 * AST * (int)sizeof(float);   // 110592 B
    cudaFuncSetAttribute(gemm_tc<true>,
                         cudaFuncAttributeMaxDynamicSharedMemorySize, gemm_smem);
    cudaFuncSetAttribute(gemm_tc<false>,
                         cudaFuncAttributeMaxDynamicSharedMemorySize, gemm_smem);
    cudaFuncSetAttribute(attn_tc,
                         cudaFuncAttributeMaxDynamicSharedMemorySize, attn_smem);

    // 0. transpose + tf32-round weights
    transpose_w<<<dim3(D / 32, D / 32, 4), dim3(32, 8)>>>(
        wq, wk, wv, wo, rwq, rwk, rwv, rwo);

    // 1. LayerNorm (tf32-rounded output)
    ln_kernel<<<ROWS, 256>>>(x, gamma, beta, xn);

    // 2. fused Q/K/V projection (rounded outputs; V staged-transposed)
    dim3 ggrid(D / 128, ROWS / 128, 3);
    gemm_tc<true><<<ggrid, 256, gemm_smem>>>(xn, rwq, rwk, rwv, bq, bk, bv,
                                             q, k, v, D, D);

    // 3. attention (rounded output)
    dim3 agrid(S / 128, B * H);
    attn_tc<<<agrid, 256, attn_smem>>>(q, k, v, att);

    // 4. output projection (fp32 output)
    dim3 ogrid(D / 128, ROWS / 128, 1);
    gemm_tc<false><<<ogrid, 256, gemm_smem>>>(att, rwo, rwo, rwo, bo, bo, bo,
                                              out, out, out, D, D);
}

// round 8
// speedup vs baseline: 4.7337x; 1.0724x over previous
#include <cuda_runtime.h>
#include <math.h>
#include <stdint.h>

// Problem constants
#define B   2
#define S   2048
#define D   1024
#define H   16
#define DH  64
#define ROWS (B*S)           // 4096
#define EPS 1e-5f

// ---------------- scratch (device globals) ---------------------------------
__device__ float g_xn [ROWS * D];
__device__ float g_q  [ROWS * D];
__device__ float g_k  [ROWS * D];
__device__ float g_v  [ROWS * D];   // TRANSPOSED: [B][D][S] = (b*D + c)*S + s
__device__ float g_att[ROWS * D];
__device__ float g_wq [D * D];      // transposed [n][k]
__device__ float g_wk [D * D];
__device__ float g_wv [D * D];
__device__ float g_wo [D * D];

// ---------------- helpers ---------------------------------------------------
__device__ __forceinline__ float cvt_tf32f(float x) {
    uint32_t u;
    asm("cvt.rna.tf32.f32 %0, %1;" : "=r"(u) : "f"(x));
    return __uint_as_float(u);
}

#define MMA_TF32(c, a, b)                                                     \
    asm volatile(                                                             \
        "mma.sync.aligned.m16n8k8.row.col.f32.tf32.tf32.f32 "                 \
        "{%0,%1,%2,%3},{%4,%5,%6,%7},{%8,%9},{%0,%1,%2,%3};"                  \
        : "+f"((c)[0]), "+f"((c)[1]), "+f"((c)[2]), "+f"((c)[3])              \
        : "r"((a)[0]), "r"((a)[1]), "r"((a)[2]), "r"((a)[3]),                 \
          "r"((b)[0]), "r"((b)[1]))

__device__ __forceinline__ uint32_t smaddr(const void* p) {
    return (uint32_t)__cvta_generic_to_shared(p);
}
#define CP_ASYNC16(dst, src)                                                  \
    asm volatile("cp.async.cg.shared.global [%0], [%1], 16;\n"                \
                 :: "r"(dst), "l"(src))
#define CP_COMMIT() asm volatile("cp.async.commit_group;\n")
#define CP_WAIT1()  asm volatile("cp.async.wait_group 1;\n")
#define CP_WAIT0()  asm volatile("cp.async.wait_group 0;\n")

// ---------------- weight transpose + tf32 round -----------------------------
__global__ void transpose_w(const float* __restrict__ a, const float* __restrict__ b,
                            const float* __restrict__ c, const float* __restrict__ d,
                            float* __restrict__ oa, float* __restrict__ ob,
                            float* __restrict__ oc, float* __restrict__ od) {
    __shared__ float t[32][33];
    const float* src = blockIdx.z == 0 ? a : blockIdx.z == 1 ? b
                     : blockIdx.z == 2 ? c : d;
    float* dst = blockIdx.z == 0 ? oa : blockIdx.z == 1 ? ob
               : blockIdx.z == 2 ? oc : od;
    int bx = blockIdx.x * 32, by = blockIdx.y * 32;
    int tx = threadIdx.x, ty = threadIdx.y;
#pragma unroll
    for (int i = 0; i < 4; i++)
        t[ty + i * 8][tx] = src[(size_t)(by + ty + i * 8) * D + bx + tx];
    __syncthreads();
#pragma unroll
    for (int i = 0; i < 4; i++)
        dst[(size_t)(bx + ty + i * 8) * D + by + tx] =
            cvt_tf32f(t[tx][ty + i * 8]);
}

// ---------------- LayerNorm (writes tf32-rounded output) --------------------
__global__ void ln_kernel(const float* __restrict__ x,
                          const float* __restrict__ gamma,
                          const float* __restrict__ beta,
                          float* __restrict__ out) {
    int row = blockIdx.x;
    const float* xr = x + (size_t)row * D;
    float* orow = out + (size_t)row * D;

    float vals[4];
    float sum = 0.f, sq = 0.f;
#pragma unroll
    for (int i = 0; i < 4; i++) {
        float v = xr[threadIdx.x + i * 256];
        vals[i] = v;
        sum += v; sq += v * v;
    }
#pragma unroll
    for (int o = 16; o >= 1; o >>= 1) {
        sum += __shfl_xor_sync(0xffffffffu, sum, o);
        sq  += __shfl_xor_sync(0xffffffffu, sq , o);
    }
    __shared__ float ssum[8], ssq[8];
    int warp = threadIdx.x >> 5, lane = threadIdx.x & 31;
    if (lane == 0) { ssum[warp] = sum; ssq[warp] = sq; }
    __syncthreads();
    float ts = 0.f, tq = 0.f;
#pragma unroll
    for (int w = 0; w < 8; w++) { ts += ssum[w]; tq += ssq[w]; }
    float mu  = ts * (1.0f / D);
    float var = tq * (1.0f / D) - mu * mu;
    float rstd = rsqrtf(var + EPS);
#pragma unroll
    for (int i = 0; i < 4; i++) {
        int c = threadIdx.x + i * 256;
        orow[c] = cvt_tf32f((vals[i] - mu) * rstd * gamma[c] + beta[c]);
    }
}

// ---------------- tf32 GEMM: 4 warps, 64x64 warp tiles, 2 CTAs/SM -----------
// Block tile 128x128, BK=32, 128 threads = 4 warps (2 M x 2 N), warp 64x64.
// B fragment reused 4x (4 m-tiles), A fragment 8x. 2-stage cp.async,
// wait -> sync -> issue(kt+1) -> compute(kt). Bit-identical accumulation.
// z==2: output staged through smem transpose, coalesced V^T stores.
#define GST 10240   // floats per stage: 128*40 (A) + 128*40 (B)

template <bool RND>
__global__ void __launch_bounds__(128, 2)
gemm_tc(const float* __restrict__ A,
        const float* __restrict__ W0, const float* __restrict__ W1,
        const float* __restrict__ W2,
        const float* __restrict__ b0, const float* __restrict__ b1,
        const float* __restrict__ b2,
        float* __restrict__ C0, float* __restrict__ C1, float* __restrict__ C2,
        int K, int N) {
    extern __shared__ float sm[];

    int z = blockIdx.z;
    const float* W = z == 0 ? W0 : z == 1 ? W1 : W2;
    const float* bias = z == 0 ? b0 : z == 1 ? b1 : b2;
    float* C = z == 0 ? C0 : z == 1 ? C1 : C2;

    int tid = threadIdx.x, lane = tid & 31, wid = tid >> 5;
    int q = lane >> 2, j = lane & 3;
    int wm = wid & 1, wn = wid >> 1;
    int mBase = blockIdx.y * 128, nBase = blockIdx.x * 128;

    float acc[4][8][4] = {};   // [mt][nt][4]

    int rl = tid >> 3, cl4 = (tid & 7) << 2;   // 16 rows x 8 float4/row

    auto issue = [&](int kt) {
        float* As = sm + (kt & 1) * GST;
        float* Bs = As + 5120;
        int k0 = kt * 32;
#pragma unroll
        for (int i = 0; i < 8; i++)
            CP_ASYNC16(smaddr(As + (rl + i * 16) * 40 + cl4),
                       A + (size_t)(mBase + rl + i * 16) * K + k0 + cl4);
#pragma unroll
        for (int i = 0; i < 8; i++)
            CP_ASYNC16(smaddr(Bs + (rl + i * 16) * 40 + cl4),
                       W + (size_t)(nBase + rl + i * 16) * K + k0 + cl4);
        CP_COMMIT();
    };

    int NT = K / 32;
    issue(0);

    for (int kt = 0; kt < NT; kt++) {
        CP_WAIT0();
        __syncthreads();
        if (kt + 1 < NT) issue(kt + 1);

        float* As = sm + (kt & 1) * GST;
        float* Bs = As + 5120;
#pragma unroll
        for (int ks = 0; ks < 4; ks++) {
            int kc = ks * 8 + 2 * j;
            uint32_t a[4][4], b[8][2];
#pragma unroll
            for (int mt = 0; mt < 4; mt++) {
                int r = wm * 64 + mt * 16 + q;
                float2 lo = *(float2*)&As[r * 40 + kc];
                float2 hi = *(float2*)&As[(r + 8) * 40 + kc];
                a[mt][0] = __float_as_uint(lo.x);
                a[mt][1] = __float_as_uint(hi.x);
                a[mt][2] = __float_as_uint(lo.y);
                a[mt][3] = __float_as_uint(hi.y);
            }
#pragma unroll
            for (int nt = 0; nt < 8; nt++) {
                int c = wn * 64 + nt * 8 + q;
                float2 w2 = *(float2*)&Bs[c * 40 + kc];
                b[nt][0] = __float_as_uint(w2.x);
                b[nt][1] = __float_as_uint(w2.y);
            }
#pragma unroll
            for (int mt = 0; mt < 4; mt++)
#pragma unroll
                for (int nt = 0; nt < 8; nt++)
                    MMA_TF32(acc[mt][nt], a[mt], b[nt]);
        }
    }

    bool transposed = (z == 2);
    if (transposed) __syncthreads();   // smem reuse: tiles no longer needed

#pragma unroll
    for (int mt = 0; mt < 4; mt++) {
        int rl0 = wm * 64 + mt * 16 + q;
        int r0 = mBase + rl0;
#pragma unroll
        for (int nt = 0; nt < 8; nt++) {
            int cl0 = wn * 64 + nt * 8 + 2 * j;
            int c0 = nBase + cl0;
            float2 b2 = *(const float2*)(bias + c0);
            float v00 = acc[mt][nt][0] + b2.x, v01 = acc[mt][nt][1] + b2.y;
            float v10 = acc[mt][nt][2] + b2.x, v11 = acc[mt][nt][3] + b2.y;
            if (RND) {
                v00 = cvt_tf32f(v00); v01 = cvt_tf32f(v01);
                v10 = cvt_tf32f(v10); v11 = cvt_tf32f(v11);
            }
            if (!transposed) {
                *(float2*)(C + (size_t)r0 * N + c0) = make_float2(v00, v01);
                *(float2*)(C + (size_t)(r0 + 8) * N + c0) = make_float2(v10, v11);
            } else {
                // stage transposed: T[c][s], pad 132 (fits: 128*132*4 < GST*2*4)
                sm[(size_t)cl0 * 132 + rl0]           = v00;
                sm[(size_t)(cl0 + 1) * 132 + rl0]     = v01;
                sm[(size_t)cl0 * 132 + rl0 + 8]       = v10;
                sm[(size_t)(cl0 + 1) * 132 + rl0 + 8] = v11;
            }
        }
    }

    if (transposed) {
        __syncthreads();
        int bb = mBase >> 11, s0 = mBase & (S - 1);
        // coalesced: 8 passes x (4 warps x 4 rows); 8 lanes cover 128B chunk
        int rowd = wid * 4 + (lane >> 3);
        int colb = (lane & 7) * 4;
#pragma unroll
        for (int ps = 0; ps < 8; ps++) {
            int c = ps * 16 + rowd;
            float* dst = C + ((size_t)(bb * D + nBase + c)) * S + s0;
            const float* srcr = sm + (size_t)c * 132;
#pragma unroll
            for (int i = 0; i < 4; i++) {
                int col = colb + i * 32;
                *(float4*)(dst + col) = *(const float4*)(srcr + col);
            }
        }
    }
}

// ---------------- flash attention: 32-row warp tiles, 2x operand reuse ------
// grid (S/128, B*H); 128 thr = 4 warps; warp w owns q-rows w*32..+31 and the
// full 64-key tile. Each K/V fragment feeds 2 MMAs (mt=0,1). PV A-fragment is
// the thread's own QK^T C-fragment. V transposed [d][s]. 3-stage cp.async
// ring, 1 sync per tile. 2 CTAs/SM.
#define AST 9216   // floats per stage: 64*72 (K) + 64*72 (V^T)

__global__ void __launch_bounds__(128, 2)
attn_tc(const float* __restrict__ Q, const float* __restrict__ K,
        const float* __restrict__ V, float* __restrict__ O) {
    extern __shared__ float sm[];

    int tid = threadIdx.x, lane = tid & 31, wid = tid >> 5;
    int q = lane >> 2, j = lane & 3;
    int bh = blockIdx.y, b = bh >> 4, h = bh & 15;
    int qbase = blockIdx.x * 128;

    const float* Kg = K + (size_t)(b * S) * D + h * DH;
    const float* VT = V + ((size_t)b * D + h * DH) * S;   // [d][s]
    const float* Qg = Q + (size_t)(b * S + qbase + wid * 32) * D + h * DH;

    int rkv = tid >> 4, ckv = (tid & 15) << 2;

    auto issue = [&](int kt) {
        float* Ks = sm + (kt % 3) * AST;
        float* Vs = Ks + 4608;
        const float* Kt = Kg + (size_t)kt * 64 * D;
        const float* Vt = VT + (size_t)kt * 64;
#pragma unroll
        for (int i = 0; i < 8; i++) {
            int r = rkv + i * 8;
            CP_ASYNC16(smaddr(Ks + r * 72 + ckv), Kt + (size_t)r * D + ckv);
            CP_ASYNC16(smaddr(Vs + r * 72 + ckv), Vt + (size_t)r * S + ckv);
        }
        CP_COMMIT();
    };

    // Q fragments for 2 m-tiles (rows q+mt*16, q+mt*16+8), scaled by 1/8
    uint32_t qf[8][2][4];
#pragma unroll
    for (int ks = 0; ks < 8; ks++) {
        int d0 = ks * 8 + 2 * j;
#pragma unroll
        for (int mt = 0; mt < 2; mt++) {
            int r = mt * 16 + q;
            float2 lo = *(const float2*)(Qg + (size_t)r * D + d0);
            float2 hi = *(const float2*)(Qg + (size_t)(r + 8) * D + d0);
            qf[ks][mt][0] = __float_as_uint(lo.x * 0.125f);
            qf[ks][mt][1] = __float_as_uint(hi.x * 0.125f);
            qf[ks][mt][2] = __float_as_uint(lo.y * 0.125f);
            qf[ks][mt][3] = __float_as_uint(hi.y * 0.125f);
        }
    }

    float o[2][8][4] = {};
    float m0[2] = {-1e30f, -1e30f}, m1[2] = {-1e30f, -1e30f};
    float l0[2] = {0.f, 0.f}, l1[2] = {0.f, 0.f};

    issue(0);
    issue(1);

    const int NKT = S / 64;
    for (int kt = 0; kt < NKT; kt++) {
        if (kt + 1 < NKT) { CP_WAIT1(); } else { CP_WAIT0(); }
        __syncthreads();

        const float* Ks = sm + (kt % 3) * AST;
        const float* Vs = Ks + 4608;

        // ---- QK^T: each K fragment feeds both m-tiles ----
        float p[2][8][4] = {};
#pragma unroll
        for (int ks = 0; ks < 8; ks++) {
            int kc = ks * 8 + 2 * j;
#pragma unroll
            for (int pr = 0; pr < 4; pr++) {
                int key0 = pr * 16 + q;
                float2 k0 = *(const float2*)&Ks[key0 * 72 + kc];
                float2 k1 = *(const float2*)&Ks[(key0 + 8) * 72 + kc];
                uint32_t bf0[2] = { __float_as_uint(k0.x), __float_as_uint(k0.y) };
                uint32_t bf1[2] = { __float_as_uint(k1.x), __float_as_uint(k1.y) };
#pragma unroll
                for (int mt = 0; mt < 2; mt++) {
                    MMA_TF32(p[mt][2 * pr], qf[ks][mt], bf0);
                    MMA_TF32(p[mt][2 * pr + 1], qf[ks][mt], bf1);
                }
            }
        }

        // ---- register online softmax per m-tile ----
        float al0[2], al1[2];
#pragma unroll
        for (int mt = 0; mt < 2; mt++) {
            float mx0 = p[mt][0][0], mx1 = p[mt][0][2];
#pragma unroll
            for (int nt = 0; nt < 8; nt++) {
                mx0 = fmaxf(mx0, fmaxf(p[mt][nt][0], p[mt][nt][1]));
                mx1 = fmaxf(mx1, fmaxf(p[mt][nt][2], p[mt][nt][3]));
            }
            mx0 = fmaxf(mx0, __shfl_xor_sync(0xffffffffu, mx0, 1));
            mx0 = fmaxf(mx0, __shfl_xor_sync(0xffffffffu, mx0, 2));
            mx1 = fmaxf(mx1, __shfl_xor_sync(0xffffffffu, mx1, 1));
            mx1 = fmaxf(mx1, __shfl_xor_sync(0xffffffffu, mx1, 2));

            float mn0 = fmaxf(m0[mt], mx0), mn1 = fmaxf(m1[mt], mx1);
            al0[mt] = __expf(m0[mt] - mn0);
            al1[mt] = __expf(m1[mt] - mn1);
            float rs0 = 0.f, rs1 = 0.f;
#pragma unroll
            for (int nt = 0; nt < 8; nt++) {
                float e0 = __expf(p[mt][nt][0] - mn0);
                float e1 = __expf(p[mt][nt][1] - mn0);
                float e2 = __expf(p[mt][nt][2] - mn1);
                float e3 = __expf(p[mt][nt][3] - mn1);
                rs0 += e0 + e1; rs1 += e2 + e3;
                p[mt][nt][0] = cvt_tf32f(e0); p[mt][nt][1] = cvt_tf32f(e1);
                p[mt][nt][2] = cvt_tf32f(e2); p[mt][nt][3] = cvt_tf32f(e3);
            }
            rs0 += __shfl_xor_sync(0xffffffffu, rs0, 1);
            rs0 += __shfl_xor_sync(0xffffffffu, rs0, 2);
            rs1 += __shfl_xor_sync(0xffffffffu, rs1, 1);
            rs1 += __shfl_xor_sync(0xffffffffu, rs1, 2);
            l0[mt] = l0[mt] * al0[mt] + rs0; m0[mt] = mn0;
            l1[mt] = l1[mt] * al1[mt] + rs1; m1[mt] = mn1;

            // rescale O
#pragma unroll
            for (int dt = 0; dt < 8; dt++) {
                o[mt][dt][0] *= al0[mt]; o[mt][dt][1] *= al0[mt];
                o[mt][dt][2] *= al1[mt]; o[mt][dt][3] *= al1[mt];
            }
        }

        // ---- PV: each V fragment feeds both m-tiles; A = own p[mt][nt] ----
#pragma unroll
        for (int nt = 0; nt < 8; nt++) {
            int kc = nt * 8 + 2 * j;
#pragma unroll
            for (int dt = 0; dt < 8; dt++) {
                float2 v2 = *(const float2*)&Vs[(dt * 8 + q) * 72 + kc];
                uint32_t bf[2] = { __float_as_uint(v2.x), __float_as_uint(v2.y) };
#pragma unroll
                for (int mt = 0; mt < 2; mt++) {
                    uint32_t af[4];
                    af[0] = __float_as_uint(p[mt][nt][0]);
                    af[1] = __float_as_uint(p[mt][nt][2]);
                    af[2] = __float_as_uint(p[mt][nt][1]);
                    af[3] = __float_as_uint(p[mt][nt][3]);
                    MMA_TF32(o[mt][dt], af, bf);
                }
            }
        }

        if (kt + 2 < NKT) issue(kt + 2);
    }

    // ---- epilogue: divide by l, write tf32-rounded ----
    float* Og = O + (size_t)(b * S + qbase + wid * 32) * D + h * DH;
#pragma unroll
    for (int mt = 0; mt < 2; mt++) {
        float il0 = 1.0f / l0[mt], il1 = 1.0f / l1[mt];
        int r = mt * 16 + q;
#pragma unroll
        for (int dt = 0; dt < 8; dt++) {
            int c0 = dt * 8 + 2 * j;
            *(float2*)(Og + (size_t)r * D + c0) =
                make_float2(cvt_tf32f(o[mt][dt][0] * il0),
                            cvt_tf32f(o[mt][dt][1] * il0));
            *(float2*)(Og + (size_t)(r + 8) * D + c0) =
                make_float2(cvt_tf32f(o[mt][dt][2] * il1),
                            cvt_tf32f(o[mt][dt][3] * il1));
        }
    }
}

// ---------------- launch ----------------------------------------------------
extern "C" void kernel_launch(void* const* d_in, const int* in_sizes, int n_in,
                              void* d_out, int out_size) {
    const float* x     = (const float*)d_in[0];
    const float* gamma = (const float*)d_in[1];
    const float* beta  = (const float*)d_in[2];
    const float* wq    = (const float*)d_in[3];
    const float* bq    = (const float*)d_in[4];
    const float* wk    = (const float*)d_in[5];
    const float* bk    = (const float*)d_in[6];
    const float* wv    = (const float*)d_in[7];
    const float* bv    = (const float*)d_in[8];
    const float* wo    = (const float*)d_in[9];
    const float* bo    = (const float*)d_in[10];
    float* out = (float*)d_out;

    float *xn, *q, *k, *v, *att, *rwq, *rwk, *rwv, *rwo;
    cudaGetSymbolAddress((void**)&xn,  g_xn);
    cudaGetSymbolAddress((void**)&q,   g_q);
    cudaGetSymbolAddress((void**)&k,   g_k);
    cudaGetSymbolAddress((void**)&v,   g_v);
    cudaGetSymbolAddress((void**)&att, g_att);
    cudaGetSymbolAddress((void**)&rwq, g_wq);
    cudaGetSymbolAddress((void**)&rwk, g_wk);
    cudaGetSymbolAddress((void**)&rwv, g_wv);
    cudaGetSymbolAddress((void**)&rwo, g_wo);

    int gemm_smem = 2 * GST * (int)sizeof(float);   // 81920 B (2 CTAs/SM)
    int attn_smem = 3 * AST * (int)sizeof(float);   // 110592 B (2 CTAs/SM)
    cudaFuncSetAttribute(gemm_tc<true>,
                         cudaFuncAttributeMaxDynamicSharedMemorySize, gemm_smem);
    cudaFuncSetAttribute(gemm_tc<false>,
                         cudaFuncAttributeMaxDynamicSharedMemorySize, gemm_smem);
    cudaFuncSetAttribute(attn_tc,
                         cudaFuncAttributeMaxDynamicSharedMemorySize, attn_smem);

    // 0. transpose + tf32-round weights
    transpose_w<<<dim3(D / 32, D / 32, 4), dim3(32, 8)>>>(
        wq, wk, wv, wo, rwq, rwk, rwv, rwo);

    // 1. LayerNorm (tf32-rounded output)
    ln_kernel<<<ROWS, 256>>>(x, gamma, beta, xn);

    // 2. fused Q/K/V projection (rounded outputs; V staged-transposed)
    dim3 ggrid(D / 128, ROWS / 128, 3);
    gemm_tc<true><<<ggrid, 128, gemm_smem>>>(xn, rwq, rwk, rwv, bq, bk, bv,
                                             q, k, v, D, D);

    // 3. attention (rounded output)
    dim3 agrid(S / 128, B * H);
    attn_tc<<<agrid, 128, attn_smem>>>(q, k, v, att);

    // 4. output projection (fp32 output)
    dim3 ogrid(D / 128, ROWS / 128, 1);
    gemm_tc<false><<<ogrid, 128, gemm_smem>>>(att, rwo, rwo, rwo, bo, bo, bo,
                                              out, out, out, D, D);
}